// round 13
// baseline (speedup 1.0000x reference)
#include <cuda_runtime.h>
#include <cuda_fp16.h>
#include <stdint.h>

#define BATCH 8
#define C 512
#define HW 16384
#define KCLS 150
#define KPAD 160
#define KP2 192
#define NSPLIT 8
#define KC 32
#define LDT 20             // u32 row stride, non-trans tiles
#define LDTT 68            // u32 row stride, trans (K-major) A tiles
#define SA (128 * LDT)
#define SB (KPAD * LDT)
#define SAT (32 * LDTT)
#define BUF_N (SA + SB)            // gemm1 / pool buffer (u32): A, B
#define BUF_T (SAT + SB)           // masks buffer (u32)
#define SMEM_G (2 * BUF_N * 4 + 2048)
#define SMEM_P (3 * BUF_N * 4 + 2048)
#define SMEM_M (3 * BUF_T * 4 + 2048)

typedef unsigned int u32;
typedef unsigned short u16;

// ---------------- scratch (device globals; no allocations) ----------------
__device__ u16  g_clsh[KPAD * C];                 // cls fp16 (zero-padded rows)
__device__ u16  g_xh[(long)BATCH * C * HW];       // x fp16
__device__ u16  g_Eh[(long)BATCH * KCLS * HW];    // E fp16
__device__ float g_colinv[BATCH * HW];
__device__ float g_rowpart[(long)BATCH * KPAD * (HW / 128)];
__device__ float g_rinv[BATCH * KPAD];
__device__ float g_poolpart[(long)NSPLIT * BATCH * KCLS * C];
__device__ float g_acls[BATCH * KCLS * C];
__device__ u16  g_aclsh[BATCH * KPAD * C];        // acls fp16 (zero-padded)
__device__ float g_clsWfp[4 * KCLS * C];          // split-K partials
__device__ float g_clsWf[KCLS * C];
__device__ u16  g_Gh[BATCH * KPAD * KP2];         // G fp16

// ---------------- helpers ----------------
__device__ __forceinline__ u32 pack2h(float v0, float v1) {
    return (u32)__half_as_ushort(__float2half_rn(v0)) |
           ((u32)__half_as_ushort(__float2half_rn(v1)) << 16);
}
__device__ __forceinline__ void mma16816h(float c[4], const u32 a[4], const u32 b[2]) {
    asm volatile(
        "mma.sync.aligned.m16n8k16.row.col.f32.f16.f16.f32 "
        "{%0,%1,%2,%3}, {%4,%5,%6,%7}, {%8,%9}, {%0,%1,%2,%3};"
        : "+f"(c[0]), "+f"(c[1]), "+f"(c[2]), "+f"(c[3])
        : "r"(a[0]), "r"(a[1]), "r"(a[2]), "r"(a[3]), "r"(b[0]), "r"(b[1]));
}
__device__ __forceinline__ void ldmat_x4(u32 r[4], const void* p) {
    u32 a = (u32)__cvta_generic_to_shared(p);
    asm volatile("ldmatrix.sync.aligned.m8n8.x4.shared.b16 {%0,%1,%2,%3}, [%4];"
                 : "=r"(r[0]), "=r"(r[1]), "=r"(r[2]), "=r"(r[3]) : "r"(a));
}
__device__ __forceinline__ void ldmat_x4t(u32 r[4], const void* p) {
    u32 a = (u32)__cvta_generic_to_shared(p);
    asm volatile("ldmatrix.sync.aligned.m8n8.x4.trans.shared.b16 {%0,%1,%2,%3}, [%4];"
                 : "=r"(r[0]), "=r"(r[1]), "=r"(r[2]), "=r"(r[3]) : "r"(a));
}
__device__ __forceinline__ void ldmat_x2(u32 r[2], const void* p) {
    u32 a = (u32)__cvta_generic_to_shared(p);
    asm volatile("ldmatrix.sync.aligned.m8n8.x2.shared.b16 {%0,%1}, [%2];"
                 : "=r"(r[0]), "=r"(r[1]) : "r"(a));
}
__device__ __forceinline__ void cpa16(void* dst, const void* src, u32 srcsz) {
    u32 d = (u32)__cvta_generic_to_shared(dst);
    asm volatile("cp.async.cg.shared.global [%0], [%1], 16, %2;"
                 :: "r"(d), "l"(src), "r"(srcsz) : "memory");
}
#define CP_COMMIT() asm volatile("cp.async.commit_group;" ::: "memory")
#define CP_WAIT0()  asm volatile("cp.async.wait_group 0;" ::: "memory")
#define CP_WAIT1()  asm volatile("cp.async.wait_group 1;" ::: "memory")

// ---- MMA cores (single fp16 term) -----------------------------------------
__device__ __forceinline__ void tile_mma(
    const u32* Ah, const u32* Bh, float (*acc)[5][4], int wm, int wn, int lane)
{
    const int arow = lane & 15, acol = (lane >> 4) << 2;
    const int brow = lane & 7,  bcol = ((lane >> 3) & 1) << 2;
    #pragma unroll
    for (int ks = 0; ks < 2; ++ks) {
        const int k2b = ks * 8;
        u32 ah[4][4];
        #pragma unroll
        for (int mi = 0; mi < 4; ++mi) {
            const int r = wm * 64 + mi * 16 + arow;
            ldmat_x4(ah[mi], Ah + r * LDT + k2b + acol);
        }
        #pragma unroll
        for (int ni = 0; ni < 5; ++ni) {
            const int nr = wn * 40 + ni * 8 + brow;
            u32 bh[2];
            ldmat_x2(bh, Bh + nr * LDT + k2b + bcol);
            #pragma unroll
            for (int mi = 0; mi < 4; ++mi)
                mma16816h(acc[mi][ni], ah[mi], bh);
        }
    }
}
// trans A: smem [K=32 rows][M=128 u16 cols], stride LDTT
__device__ __forceinline__ void tile_mma_t(
    const u32* Ah, const u32* Bh, float (*acc)[5][4], int wm, int wn, int lane)
{
    const int kr = (lane & 7) + ((lane >> 4) << 3);
    const int mo = ((lane >> 3) & 1) << 3;
    const int brow = lane & 7, bcol = ((lane >> 3) & 1) << 2;
    #pragma unroll
    for (int ks = 0; ks < 2; ++ks) {
        const int k2b = ks * 8;
        u32 ah[4][4];
        #pragma unroll
        for (int mi = 0; mi < 4; ++mi) {
            const int m = wm * 64 + mi * 16 + mo;
            ldmat_x4t(ah[mi], (const u16*)(Ah + (ks * 16 + kr) * LDTT) + m);
        }
        #pragma unroll
        for (int ni = 0; ni < 5; ++ni) {
            const int nr = wn * 40 + ni * 8 + brow;
            u32 bh[2];
            ldmat_x2(bh, Bh + nr * LDT + k2b + bcol);
            #pragma unroll
            for (int mi = 0; mi < 4; ++mi)
                mma16816h(acc[mi][ni], ah[mi], bh);
        }
    }
}

// B fill via cp.async (160 rows x 64B = 640 chunks); B sits at offset aoffs in buf
__device__ __forceinline__ void cpB1(u32* buf, long aoffs, int t, const u16* bh,
                                     long rs, long colbase, int rows_valid) {
    #pragma unroll
    for (int ii = 0; ii < 3; ++ii) {
        int i = t + 256 * ii;
        if (i < 640) {
            int row = i >> 2, q = i & 3;
            int rc = row < rows_valid ? row : rows_valid - 1;
            const u16* s = bh + (long)rc * rs + colbase + q * 8;
            char* d = (char*)(buf + aoffs) + row * 80 + q * 16;
            cpa16(d, s, row < rows_valid ? 16u : 0u);
        }
    }
}

// ===========================================================================
// GEMM1: D[n=128,k=160] = x^T·cls ; manual A (emits xh), cp.async B (cls).
// ===========================================================================
__device__ __forceinline__ void g1_storeA(u32* buf, int n, int half, const float* pxa,
                                          u16* xh, long gbase) {
    u32 hvs[8];
    #pragma unroll
    for (int j = 0; j < 8; ++j) hvs[j] = pack2h(pxa[2 * j], pxa[2 * j + 1]);
    u32* a = buf + n * LDT + half * 8;
    *(uint4*)(a)     = make_uint4(hvs[0], hvs[1], hvs[2], hvs[3]);
    *(uint4*)(a + 4) = make_uint4(hvs[4], hvs[5], hvs[6], hvs[7]);
    #pragma unroll
    for (int j = 0; j < 8; ++j) {
        long o = gbase + (long)(2 * j) * HW;
        xh[o]      = (u16)(hvs[j] & 0xFFFF);
        xh[o + HW] = (u16)(hvs[j] >> 16);
    }
}

__global__ __launch_bounds__(256) void k_gemm1_mma(
    const float* __restrict__ x, const u16* __restrict__ clsh,
    u16* __restrict__ Eh, u16* __restrict__ xh,
    float* __restrict__ colinv, float* __restrict__ rowpart)
{
    extern __shared__ u32 sm[];
    float* srow  = (float*)(sm + 2 * BUF_N);
    float* skrow = srow + 128;
    const int t = threadIdx.x;
    const int wid = t >> 5, lane = t & 31, g = lane >> 2, tid = lane & 3;
    const int wm = wid >> 2, wn = wid & 3;
    const int n0 = blockIdx.x * 128, b = blockIdx.y;
    if (t < 128) srow[t] = 0.f;
    if (t < KPAD) skrow[t] = 0.f;

    float acc[4][5][4] = {};
    const int n = t & 127, half = t >> 7;
    const float* xb = x + (long)b * C * HW + n0 + n;

    float pxa[16];
    #pragma unroll
    for (int j = 0; j < 8; ++j) {
        int c = (half * 8 + j) * 2;
        pxa[2 * j] = xb[(long)c * HW]; pxa[2 * j + 1] = xb[(long)(c + 1) * HW];
    }
    g1_storeA(sm, n, half, pxa, xh, ((long)b * C + half * 16) * HW + n0 + n);
    cpB1(sm, SA, t, clsh, C, 0, KPAD);
    CP_COMMIT(); CP_WAIT0();
    __syncthreads();

    #pragma unroll 1
    for (int cc = 0; cc < C / KC; ++cc) {
        if (cc + 1 < C / KC) {
            #pragma unroll
            for (int j = 0; j < 8; ++j) {
                int c = (cc + 1) * KC + (half * 8 + j) * 2;
                pxa[2 * j] = xb[(long)c * HW]; pxa[2 * j + 1] = xb[(long)(c + 1) * HW];
            }
            u32* nb = sm + ((cc + 1) & 1) * BUF_N;
            cpB1(nb, SA, t, clsh, C, (cc + 1) * 32, KPAD);
            CP_COMMIT();
        }
        u32* cb_ = sm + (cc & 1) * BUF_N;
        tile_mma(cb_, cb_ + SA, acc, wm, wn, lane);
        if (cc + 1 < C / KC) {
            u32* nb = sm + ((cc + 1) & 1) * BUF_N;
            g1_storeA(nb, n, half, pxa, xh,
                      ((long)b * C + (cc + 1) * 32 + half * 16) * HW + n0 + n);
            CP_WAIT0();
            __syncthreads();
        }
    }

    #pragma unroll
    for (int mi = 0; mi < 4; ++mi) {
        const int r0 = wm * 64 + mi * 16 + g;
        float s0 = 0.f, s1 = 0.f;
        #pragma unroll
        for (int ni = 0; ni < 5; ++ni) {
            const int cb = wn * 40 + ni * 8 + tid * 2;
            float e0 = __expf(acc[mi][ni][0]);
            float e1 = __expf(acc[mi][ni][1]);
            float e2 = __expf(acc[mi][ni][2]);
            float e3 = __expf(acc[mi][ni][3]);
            float vk0 = 0.f, vk1 = 0.f;
            if (cb < KCLS) {
                long o0 = ((long)b * KCLS + cb) * HW + n0 + r0;
                Eh[o0]     = __half_as_ushort(__float2half_rn(e0));
                Eh[o0 + 8] = __half_as_ushort(__float2half_rn(e2));
                s0 += e0; s1 += e2; vk0 = e0 + e2;
            }
            if (cb + 1 < KCLS) {
                long o1 = ((long)b * KCLS + cb + 1) * HW + n0 + r0;
                Eh[o1]     = __half_as_ushort(__float2half_rn(e1));
                Eh[o1 + 8] = __half_as_ushort(__float2half_rn(e3));
                s0 += e1; s1 += e3; vk1 = e1 + e3;
            }
            vk0 += __shfl_xor_sync(0xFFFFFFFFu, vk0, 4);
            vk0 += __shfl_xor_sync(0xFFFFFFFFu, vk0, 8);
            vk0 += __shfl_xor_sync(0xFFFFFFFFu, vk0, 16);
            vk1 += __shfl_xor_sync(0xFFFFFFFFu, vk1, 4);
            vk1 += __shfl_xor_sync(0xFFFFFFFFu, vk1, 8);
            vk1 += __shfl_xor_sync(0xFFFFFFFFu, vk1, 16);
            if (g == 0 && cb < KCLS) {
                atomicAdd(&skrow[cb], vk0);
                if (cb + 1 < KCLS) atomicAdd(&skrow[cb + 1], vk1);
            }
        }
        atomicAdd(&srow[r0], s0);
        atomicAdd(&srow[r0 + 8], s1);
    }
    __syncthreads();
    if (t < 128) colinv[(long)b * HW + n0 + t] = 1.f / srow[t];
    if (t < KPAD)
        rowpart[((long)b * KPAD + t) * (HW / 128) + blockIdx.x] = skrow[t];
}

// ===========================================================================
// pool: D[c=128,k=160] = sum_n x[c,n]*E[k,n] — triple-buffered cp.async.
// ===========================================================================
__device__ __forceinline__ void pool_fill(u32* buf, int t, int b, int c0, int nb,
                                          const u16* xh, const u16* Eh) {
    #pragma unroll
    for (int ii = 0; ii < 2; ++ii) {
        int i = t + 256 * ii;          // 0..511 : A = x (128 rows x 4 chunks)
        int row = i >> 2, q = i & 3;
        const u16* s = xh + ((long)b * C + c0 + row) * HW + nb + q * 8;
        char* d = (char*)buf + row * 80 + q * 16;
        cpa16(d, s, 16);
    }
    #pragma unroll
    for (int ii = 0; ii < 3; ++ii) {
        int i = t + 256 * ii;
        if (i < 640) {
            int row = i >> 2, q = i & 3;
            int rc = row < KCLS ? row : KCLS - 1;
            const u16* s = Eh + ((long)b * KCLS + rc) * HW + nb + q * 8;
            char* d = (char*)(buf + SA) + row * 80 + q * 16;
            cpa16(d, s, row < KCLS ? 16u : 0u);
        }
    }
}

__global__ __launch_bounds__(256, 2) void k_pool_mma(
    const u16* __restrict__ xh, const u16* __restrict__ Eh,
    float* __restrict__ poolpart)
{
    extern __shared__ u32 sm[];
    const int t = threadIdx.x;
    const int wid = t >> 5, lane = t & 31, g = lane >> 2, tid = lane & 3;
    const int wm = wid >> 2, wn = wid & 3;
    const int c0 = blockIdx.x * 128, sp = blockIdx.y, b = blockIdx.z;
    const int nbase = sp * (HW / NSPLIT);
    const int NCH = (HW / NSPLIT) / KC;
    float acc[4][5][4] = {};

    pool_fill(sm, t, b, c0, nbase, xh, Eh);
    CP_COMMIT();
    pool_fill(sm + BUF_N, t, b, c0, nbase + KC, xh, Eh);
    CP_COMMIT();

    #pragma unroll 1
    for (int cc = 0; cc < NCH; ++cc) {
        CP_WAIT1();
        __syncthreads();
        if (cc + 2 < NCH) {
            pool_fill(sm + ((cc + 2) % 3) * BUF_N, t, b, c0, nbase + (cc + 2) * KC,
                      xh, Eh);
            CP_COMMIT();
        }
        u32* cb_ = sm + (cc % 3) * BUF_N;
        tile_mma(cb_, cb_ + SA, acc, wm, wn, lane);
    }

    const long base = ((long)sp * BATCH + b) * KCLS;
    #pragma unroll
    for (int mi = 0; mi < 4; ++mi) {
        const int r0 = wm * 64 + mi * 16 + g;
        #pragma unroll
        for (int ni = 0; ni < 5; ++ni) {
            const int cb = wn * 40 + ni * 8 + tid * 2;
            if (cb < KCLS) {
                poolpart[(base + cb) * C + c0 + r0]     = acc[mi][ni][0];
                poolpart[(base + cb) * C + c0 + r0 + 8] = acc[mi][ni][2];
            }
            if (cb + 1 < KCLS) {
                poolpart[(base + cb + 1) * C + c0 + r0]     = acc[mi][ni][1];
                poolpart[(base + cb + 1) * C + c0 + r0 + 8] = acc[mi][ni][3];
            }
        }
    }
}

// ===========================================================================
// masks: phase2 (E·G) first, scale by ci, then phase1 (x^T·acls); LN epilogue.
// Triple-buffered cp.async.
// ===========================================================================
__device__ __forceinline__ void masks_fillA(u32* buf, int t, const u16* ah_,
                                            long rowbase, long rowlimit, long stride,
                                            long colbase) {
    #pragma unroll
    for (int ii = 0; ii < 2; ++ii) {
        int i = t + 256 * ii;          // 0..511 : 32 rows x 16 chunks
        int row = i >> 4, q = i & 15;
        long r = rowbase + row;
        long rc = r < rowlimit ? r : rowlimit - 1;
        const u16* s = ah_ + rc * stride + colbase + q * 8;
        char* d = (char*)buf + row * (LDTT * 4) + q * 16;
        cpa16(d, s, r < rowlimit ? 16u : 0u);
    }
}
__device__ __forceinline__ void masks_fill_chunk(
    u32* nb, int jf, int t, int NCH2,
    const u16* Eh, const u16* xh, const u16* gb_h, const u16* ab_h,
    long eb, long xbge, int n0) {
    if (jf < NCH2) {
        masks_fillA(nb, t, Eh, eb + jf * 32, eb + KCLS, HW, n0);
        cpB1(nb, SAT, t, gb_h, KP2, jf * 32, KPAD);
    } else {
        const int cc = jf - NCH2;
        masks_fillA(nb, t, xh, xbge + cc * 32, xbge + C, HW, n0);
        cpB1(nb, SAT, t, ab_h, C, cc * 32, KPAD);
    }
}

__global__ __launch_bounds__(256, 2) void k_masks_mma(
    const u16* __restrict__ xh, const u16* __restrict__ aclsh,
    const u16* __restrict__ Gh, const u16* __restrict__ Eh,
    const float* __restrict__ colinv,
    const float* __restrict__ gamma, const float* __restrict__ beta,
    float* __restrict__ out)
{
    extern __shared__ u32 sm[];
    float* ssum = (float*)(sm + 3 * BUF_T);
    float* ssq  = ssum + 128;
    float* civ  = ssq + 128;
    const int t = threadIdx.x;
    const int wid = t >> 5, lane = t & 31, g = lane >> 2, tid = lane & 3;
    const int wm = wid >> 2, wn = wid & 3;
    const int n0 = blockIdx.x * 128, b = blockIdx.y;
    if (t < 128) {
        ssum[t] = 0.f; ssq[t] = 0.f;
        civ[t] = colinv[(long)b * HW + n0 + t];
    }

    float acc[4][5][4] = {};
    const u16* ab_h = aclsh + (long)b * KPAD * C;
    const u16* gb_h = Gh + (long)b * KPAD * KP2;
    const long eb = (long)b * KCLS;
    const long xbge = (long)b * C;
    const int NCH2 = KP2 / KC;          // 6 (phase 2 first)
    const int NCH  = NCH2 + C / KC;     // 22

    masks_fill_chunk(sm, 0, t, NCH2, Eh, xh, gb_h, ab_h, eb, xbge, n0);
    CP_COMMIT();
    masks_fill_chunk(sm + BUF_T, 1, t, NCH2, Eh, xh, gb_h, ab_h, eb, xbge, n0);
    CP_COMMIT();

    #pragma unroll 1
    for (int j = 0; j < NCH; ++j) {
        CP_WAIT1();
        __syncthreads();
        if (j + 2 < NCH) {
            masks_fill_chunk(sm + ((j + 2) % 3) * BUF_T, j + 2, t, NCH2,
                             Eh, xh, gb_h, ab_h, eb, xbge, n0);
            CP_COMMIT();
        }
        u32* cb_ = sm + (j % 3) * BUF_T;
        tile_mma_t(cb_, cb_ + SAT, acc, wm, wn, lane);
        if (j == NCH2 - 1) {
            #pragma unroll
            for (int mi = 0; mi < 4; ++mi) {
                const int r0 = wm * 64 + mi * 16 + g;
                const float c0v = civ[r0], c1v = civ[r0 + 8];
                #pragma unroll
                for (int ni = 0; ni < 5; ++ni) {
                    acc[mi][ni][0] *= c0v; acc[mi][ni][1] *= c0v;
                    acc[mi][ni][2] *= c1v; acc[mi][ni][3] *= c1v;
                }
            }
        }
    }

    // LayerNorm over k (<150)
    #pragma unroll
    for (int mi = 0; mi < 4; ++mi) {
        const int r0 = wm * 64 + mi * 16 + g;
        float s0 = 0.f, q0 = 0.f, s1 = 0.f, q1 = 0.f;
        #pragma unroll
        for (int ni = 0; ni < 5; ++ni) {
            const int cb = wn * 40 + ni * 8 + tid * 2;
            if (cb < KCLS) {
                float v = acc[mi][ni][0]; s0 += v; q0 += v * v;
                v = acc[mi][ni][2]; s1 += v; q1 += v * v;
            }
            if (cb + 1 < KCLS) {
                float v = acc[mi][ni][1]; s0 += v; q0 += v * v;
                v = acc[mi][ni][3]; s1 += v; q1 += v * v;
            }
        }
        atomicAdd(&ssum[r0], s0); atomicAdd(&ssq[r0], q0);
        atomicAdd(&ssum[r0 + 8], s1); atomicAdd(&ssq[r0 + 8], q1);
    }
    __syncthreads();
    #pragma unroll
    for (int mi = 0; mi < 4; ++mi) {
        const int r0 = wm * 64 + mi * 16 + g;
        const float mu0 = ssum[r0] * (1.f / KCLS);
        const float rs0 = rsqrtf(ssq[r0] * (1.f / KCLS) - mu0 * mu0 + 1e-5f);
        const float mu1 = ssum[r0 + 8] * (1.f / KCLS);
        const float rs1 = rsqrtf(ssq[r0 + 8] * (1.f / KCLS) - mu1 * mu1 + 1e-5f);
        #pragma unroll
        for (int ni = 0; ni < 5; ++ni) {
            const int cb = wn * 40 + ni * 8 + tid * 2;
            if (cb < KCLS) {
                float ga = gamma[cb], be = beta[cb];
                out[((long)b * KCLS + cb) * HW + n0 + r0] =
                    (acc[mi][ni][0] - mu0) * rs0 * ga + be;
                out[((long)b * KCLS + cb) * HW + n0 + r0 + 8] =
                    (acc[mi][ni][2] - mu1) * rs1 * ga + be;
            }
            if (cb + 1 < KCLS) {
                float ga = gamma[cb + 1], be = beta[cb + 1];
                out[((long)b * KCLS + cb + 1) * HW + n0 + r0] =
                    (acc[mi][ni][1] - mu0) * rs0 * ga + be;
                out[((long)b * KCLS + cb + 1) * HW + n0 + r0 + 8] =
                    (acc[mi][ni][3] - mu1) * rs1 * ga + be;
            }
        }
    }
}

// ===========================================================================
// SIMT small kernels
// ===========================================================================
__global__ void k_prep(const float* __restrict__ cls, u16* __restrict__ ch_)
{
    int i = blockIdx.x * 256 + threadIdx.x;
    if (i < KPAD * C) {
        float v = (i < KCLS * C) ? cls[i] : 0.f;
        ch_[i] = __half_as_ushort(__float2half_rn(v));
    }
}

__global__ void k_rowred(const float* __restrict__ rowpart, float* __restrict__ rinv)
{
    int idx = blockIdx.x * 256 + threadIdx.x;
    if (idx < BATCH * KPAD) {
        const float* p = rowpart + (long)idx * (HW / 128);
        float s = 0.f;
        for (int i = 0; i < HW / 128; ++i) s += p[i];
        rinv[idx] = 1.f / s;
    }
}

// bounded-K small GEMM body: out = A(kxC rows)[:, pbeg:pend] * W(cxC rows)^T
__device__ __forceinline__ void sg_body(
    const float* __restrict__ A, int arow_valid, const float* __restrict__ W, int brow_valid,
    float acc[4][4], int t, float As[16][64], float Bs[16][64], int pbeg, int pend)
{
    const int tm = (t >> 4) * 4, tn = (t & 15) * 4;
    const int ar = t >> 2, ac = (t & 3) * 4;
    const int bc = t >> 2, bp = (t & 3) * 4;
    for (int p0 = pbeg; p0 < pend; p0 += 16) {
        float4 av = make_float4(0.f, 0.f, 0.f, 0.f);
        if (ar < arow_valid) av = *(const float4*)&A[(long)ar * C + p0 + ac];
        As[ac + 0][ar] = av.x; As[ac + 1][ar] = av.y; As[ac + 2][ar] = av.z; As[ac + 3][ar] = av.w;
        float4 bv = make_float4(0.f, 0.f, 0.f, 0.f);
        if (bc < brow_valid) bv = *(const float4*)&W[(long)bc * C + p0 + bp];
        Bs[bp + 0][bc] = bv.x; Bs[bp + 1][bc] = bv.y; Bs[bp + 2][bc] = bv.z; Bs[bp + 3][bc] = bv.w;
        __syncthreads();
        #pragma unroll
        for (int kk = 0; kk < 16; ++kk) {
            float4 a4 = *(const float4*)&As[kk][tm];
            float4 b4 = *(const float4*)&Bs[kk][tn];
            float aa[4] = {a4.x, a4.y, a4.z, a4.w};
            float bb[4] = {b4.x, b4.y, b4.z, b4.w};
            #pragma unroll
            for (int i = 0; i < 4; ++i)
                #pragma unroll
                for (int j = 0; j < 4; ++j)
                    acc[i][j] = fmaf(aa[i], bb[j], acc[i][j]);
        }
        __syncthreads();
    }
}

// clsWf split-K partials: grid (3, 8, 4)
__global__ __launch_bounds__(256) void k_clsWf(
    const float* __restrict__ cls, const float* __restrict__ W, float* __restrict__ outp)
{
    __shared__ float As[16][64], Bs[16][64];
    const int t = threadIdx.x, k0 = blockIdx.x * 64, c0 = blockIdx.y * 64;
    const int z = blockIdx.z;
    float acc[4][4] = {};
    int av = KCLS - k0; av = av > 64 ? 64 : (av > 0 ? av : 0);
    sg_body(cls + (long)k0 * C, av, W + (long)c0 * C, 64, acc, t, As, Bs,
            z * 128, z * 128 + 128);
    const int tm = (t >> 4) * 4, tn = (t & 15) * 4;
    #pragma unroll
    for (int i = 0; i < 4; ++i) {
        int k = k0 + tm + i;
        if (k < KCLS)
            *(float4*)&outp[(long)z * KCLS * C + (long)k * C + c0 + tn] =
                make_float4(acc[i][0], acc[i][1], acc[i][2], acc[i][3]);
    }
}

__global__ void k_red4(const float* __restrict__ p, float* __restrict__ o)
{
    int i = blockIdx.x * 256 + threadIdx.x;
    if (i < KCLS * C)
        o[i] = p[i] + p[KCLS * C + i] + p[2 * KCLS * C + i] + p[3 * KCLS * C + i];
}

__global__ __launch_bounds__(256) void k_acls(
    const float* __restrict__ poolpart, const float* __restrict__ rinv,
    const float* __restrict__ W, const float* __restrict__ cls,
    float* __restrict__ outf, u16* __restrict__ outh)
{
    __shared__ float As[16][64], Bs[16][64];
    const int t = threadIdx.x;
    const int k0 = blockIdx.x * 64, c0 = blockIdx.y * 64, b = blockIdx.z;
    const int tm = (t >> 4) * 4, tn = (t & 15) * 4;
    const int ar = t >> 2, ac = (t & 3) * 4;
    const int bc = t >> 2, bp = (t & 3) * 4;
    float acc[4][4] = {};
    const int ka = k0 + ar;
    const float rv = (ka < KCLS) ? rinv[b * KPAD + ka] : 0.f;

    for (int p0 = 0; p0 < C; p0 += 16) {
        float4 av = make_float4(0.f, 0.f, 0.f, 0.f);
        if (ka < KCLS) {
            #pragma unroll
            for (int s = 0; s < NSPLIT; ++s) {
                float4 v = *(const float4*)
                    &poolpart[(((long)s * BATCH + b) * KCLS + ka) * C + p0 + ac];
                av.x += v.x; av.y += v.y; av.z += v.z; av.w += v.w;
            }
            av.x *= rv; av.y *= rv; av.z *= rv; av.w *= rv;
        }
        As[ac + 0][ar] = av.x; As[ac + 1][ar] = av.y; As[ac + 2][ar] = av.z; As[ac + 3][ar] = av.w;
        float4 bv = *(const float4*)&W[(long)(c0 + bc) * C + p0 + bp];
        Bs[bp + 0][bc] = bv.x; Bs[bp + 1][bc] = bv.y; Bs[bp + 2][bc] = bv.z; Bs[bp + 3][bc] = bv.w;
        __syncthreads();
        #pragma unroll
        for (int kk = 0; kk < 16; ++kk) {
            float4 a4 = *(const float4*)&As[kk][tm];
            float4 b4 = *(const float4*)&Bs[kk][tn];
            float aa[4] = {a4.x, a4.y, a4.z, a4.w};
            float bb[4] = {b4.x, b4.y, b4.z, b4.w};
            #pragma unroll
            for (int i = 0; i < 4; ++i)
                #pragma unroll
                for (int j = 0; j < 4; ++j)
                    acc[i][j] = fmaf(aa[i], bb[j], acc[i][j]);
        }
        __syncthreads();
    }
    #pragma unroll
    for (int i = 0; i < 4; ++i) {
        int k = k0 + tm + i;
        if (k < KCLS) {
            #pragma unroll
            for (int j = 0; j < 4; ++j) {
                float v = acc[i][j] + cls[(long)k * C + c0 + tn + j];
                outf[((long)b * KCLS + k) * C + c0 + tn + j] = v;
                outh[((long)b * KPAD + k) * C + c0 + tn + j] =
                    __half_as_ushort(__float2half_rn(v));
            }
        } else if (k < KPAD) {
            #pragma unroll
            for (int j = 0; j < 4; ++j)
                outh[((long)b * KPAD + k) * C + c0 + tn + j] = 0;
        }
    }
}

__global__ __launch_bounds__(256) void k_G(
    const float* __restrict__ acls, const float* __restrict__ clsWf,
    u16* __restrict__ Gh)
{
    __shared__ float As[16][64], Bs[16][64];
    const int t = threadIdx.x;
    const int k0 = blockIdx.x * 64, k20 = blockIdx.y * 64, b = blockIdx.z;
    float acc[4][4] = {};
    int av = KCLS - k0; av = av > 64 ? 64 : (av > 0 ? av : 0);
    int bv = KCLS - k20; bv = bv > 64 ? 64 : (bv > 0 ? bv : 0);
    sg_body(acls + ((long)b * KCLS + k0) * C, av, clsWf + (long)k20 * C, bv,
            acc, t, As, Bs, 0, C);
    const int tm = (t >> 4) * 4, tn = (t & 15) * 4;
    #pragma unroll
    for (int i = 0; i < 4; ++i) {
        int k = k0 + tm + i;
        if (k < KPAD) {
            #pragma unroll
            for (int j = 0; j < 4; ++j)
                Gh[((long)b * KPAD + k) * KP2 + k20 + tn + j] =
                    __half_as_ushort(__float2half_rn(acc[i][j]));
        }
    }
}

// ===========================================================================
extern "C" void kernel_launch(void* const* d_in, const int* in_sizes, int n_in,
                              void* d_out, int out_size)
{
    const float* x     = (const float*)d_in[0];
    const float* cls   = (const float*)d_in[1];
    const float* Wcls  = (const float*)d_in[2];
    const float* Wfeat = (const float*)d_in[3];
    const float* gamma = (const float*)d_in[4];
    const float* beta  = (const float*)d_in[5];
    float* out = (float*)d_out;

    u16 *clsh, *aclsh, *Gh, *Eh, *xh;
    float *colinv, *rowpart, *rinv, *poolpart, *acls, *clsWfp, *clsWf;
    cudaGetSymbolAddress((void**)&clsh,  g_clsh);
    cudaGetSymbolAddress((void**)&Eh,    g_Eh);
    cudaGetSymbolAddress((void**)&xh,    g_xh);
    cudaGetSymbolAddress((void**)&colinv, g_colinv);
    cudaGetSymbolAddress((void**)&rowpart, g_rowpart);
    cudaGetSymbolAddress((void**)&rinv,  g_rinv);
    cudaGetSymbolAddress((void**)&poolpart, g_poolpart);
    cudaGetSymbolAddress((void**)&acls,  g_acls);
    cudaGetSymbolAddress((void**)&aclsh, g_aclsh);
    cudaGetSymbolAddress((void**)&clsWfp, g_clsWfp);
    cudaGetSymbolAddress((void**)&clsWf, g_clsWf);
    cudaGetSymbolAddress((void**)&Gh,    g_Gh);

    cudaFuncSetAttribute(k_gemm1_mma, cudaFuncAttributeMaxDynamicSharedMemorySize, SMEM_G);
    cudaFuncSetAttribute(k_pool_mma,  cudaFuncAttributeMaxDynamicSharedMemorySize, SMEM_P);
    cudaFuncSetAttribute(k_masks_mma, cudaFuncAttributeMaxDynamicSharedMemorySize, SMEM_M);

    k_prep<<<(KPAD * C + 255) / 256, 256>>>(cls, clsh);
    k_gemm1_mma<<<dim3(HW / 128, BATCH), 256, SMEM_G>>>(
        x, clsh, Eh, xh, colinv, rowpart);
    k_rowred<<<(BATCH * KPAD + 255) / 256, 256>>>(rowpart, rinv);
    k_pool_mma<<<dim3(C / 128, NSPLIT, BATCH), 256, SMEM_P>>>(xh, Eh, poolpart);
    k_clsWf<<<dim3(3, C / 64, 4), 256>>>(cls, Wfeat, clsWfp);
    k_red4<<<(KCLS * C + 255) / 256, 256>>>(clsWfp, clsWf);
    k_acls<<<dim3(3, C / 64, BATCH), 256>>>(poolpart, rinv, Wcls, cls, acls, aclsh);
    k_G<<<dim3(3, 3, BATCH), 256>>>(acls, clsWf, Gh);
    k_masks_mma<<<dim3(HW / 128, BATCH), 256, SMEM_M>>>(
        xh, aclsh, Gh, Eh, colinv, gamma, beta, out);
}

// round 14
// speedup vs baseline: 1.3916x; 1.3916x over previous
#include <cuda_runtime.h>
#include <cuda_fp16.h>
#include <stdint.h>

#define BATCH 8
#define C 512
#define HW 16384
#define KCLS 150
#define KPAD 160
#define KP2 192
#define NSPLIT 16
#define KC 32
#define LDT 20             // u32 row stride, non-trans tiles
#define LDTT 68            // u32 row stride, trans (K-major) A tiles
#define SA (128 * LDT)
#define SB (KPAD * LDT)
#define SAT (32 * LDTT)
#define BUF_N (SA + SB)            // gemm1 / pool buffer (u32): A, B
#define BUF_T (SAT + SB)           // masks buffer (u32)
#define SMEM_N (2 * BUF_N * 4 + 2048)
#define SMEM_T (2 * BUF_T * 4 + 2048)

typedef unsigned int u32;
typedef unsigned short u16;

// ---------------- scratch (device globals; no allocations) ----------------
__device__ u16  g_clsh[KPAD * C];                 // cls fp16 (zero-padded rows)
__device__ u16  g_xh[(long)BATCH * C * HW];       // x fp16
__device__ u16  g_Eh[(long)BATCH * KCLS * HW];    // E fp16
__device__ float g_colinv[BATCH * HW];
__device__ float g_rowpart[(long)BATCH * KPAD * (HW / 128)];
__device__ float g_rinv[BATCH * KPAD];
__device__ float g_poolpart[(long)NSPLIT * BATCH * KCLS * C];
__device__ float g_acls[BATCH * KCLS * C];
__device__ u16  g_aclsh[BATCH * KPAD * C];        // acls fp16 (zero-padded)
__device__ float g_clsWfp[4 * KCLS * C];          // split-K partials
__device__ float g_clsWf[KCLS * C];
__device__ u16  g_Gh[BATCH * KPAD * KP2];         // G fp16

// ---------------- helpers ----------------
__device__ __forceinline__ u32 pack2h(float v0, float v1) {
    return (u32)__half_as_ushort(__float2half_rn(v0)) |
           ((u32)__half_as_ushort(__float2half_rn(v1)) << 16);
}
__device__ __forceinline__ void mma16816h(float c[4], const u32 a[4], const u32 b[2]) {
    asm volatile(
        "mma.sync.aligned.m16n8k16.row.col.f32.f16.f16.f32 "
        "{%0,%1,%2,%3}, {%4,%5,%6,%7}, {%8,%9}, {%0,%1,%2,%3};"
        : "+f"(c[0]), "+f"(c[1]), "+f"(c[2]), "+f"(c[3])
        : "r"(a[0]), "r"(a[1]), "r"(a[2]), "r"(a[3]), "r"(b[0]), "r"(b[1]));
}
__device__ __forceinline__ void ldmat_x4(u32 r[4], const void* p) {
    u32 a = (u32)__cvta_generic_to_shared(p);
    asm volatile("ldmatrix.sync.aligned.m8n8.x4.shared.b16 {%0,%1,%2,%3}, [%4];"
                 : "=r"(r[0]), "=r"(r[1]), "=r"(r[2]), "=r"(r[3]) : "r"(a));
}
__device__ __forceinline__ void ldmat_x4t(u32 r[4], const void* p) {
    u32 a = (u32)__cvta_generic_to_shared(p);
    asm volatile("ldmatrix.sync.aligned.m8n8.x4.trans.shared.b16 {%0,%1,%2,%3}, [%4];"
                 : "=r"(r[0]), "=r"(r[1]), "=r"(r[2]), "=r"(r[3]) : "r"(a));
}
__device__ __forceinline__ void ldmat_x2(u32 r[2], const void* p) {
    u32 a = (u32)__cvta_generic_to_shared(p);
    asm volatile("ldmatrix.sync.aligned.m8n8.x2.shared.b16 {%0,%1}, [%2];"
                 : "=r"(r[0]), "=r"(r[1]) : "r"(a));
}
__device__ __forceinline__ void cpa16(void* dst, const void* src, u32 srcsz) {
    u32 d = (u32)__cvta_generic_to_shared(dst);
    asm volatile("cp.async.cg.shared.global [%0], [%1], 16, %2;"
                 :: "r"(d), "l"(src), "r"(srcsz) : "memory");
}
#define CP_COMMIT() asm volatile("cp.async.commit_group;" ::: "memory")
#define CP_WAIT0()  asm volatile("cp.async.wait_group 0;" ::: "memory")

// ---- MMA cores (single fp16 term) -----------------------------------------
__device__ __forceinline__ void tile_mma(
    const u32* Ah, const u32* Bh, float (*acc)[5][4], int wm, int wn, int lane)
{
    const int arow = lane & 15, acol = (lane >> 4) << 2;
    const int brow = lane & 7,  bcol = ((lane >> 3) & 1) << 2;
    #pragma unroll
    for (int ks = 0; ks < 2; ++ks) {
        const int k2b = ks * 8;
        u32 ah[4][4];
        #pragma unroll
        for (int mi = 0; mi < 4; ++mi) {
            const int r = wm * 64 + mi * 16 + arow;
            ldmat_x4(ah[mi], Ah + r * LDT + k2b + acol);
        }
        #pragma unroll
        for (int ni = 0; ni < 5; ++ni) {
            const int nr = wn * 40 + ni * 8 + brow;
            u32 bh[2];
            ldmat_x2(bh, Bh + nr * LDT + k2b + bcol);
            #pragma unroll
            for (int mi = 0; mi < 4; ++mi)
                mma16816h(acc[mi][ni], ah[mi], bh);
        }
    }
}
// trans A: smem [K=32 rows][M=128 u16 cols], stride LDTT
__device__ __forceinline__ void tile_mma_t(
    const u32* Ah, const u32* Bh, float (*acc)[5][4], int wm, int wn, int lane)
{
    const int kr = (lane & 7) + ((lane >> 4) << 3);
    const int mo = ((lane >> 3) & 1) << 3;
    const int brow = lane & 7, bcol = ((lane >> 3) & 1) << 2;
    #pragma unroll
    for (int ks = 0; ks < 2; ++ks) {
        const int k2b = ks * 8;
        u32 ah[4][4];
        #pragma unroll
        for (int mi = 0; mi < 4; ++mi) {
            const int m = wm * 64 + mi * 16 + mo;
            ldmat_x4t(ah[mi], (const u16*)(Ah + (ks * 16 + kr) * LDTT) + m);
        }
        #pragma unroll
        for (int ni = 0; ni < 5; ++ni) {
            const int nr = wn * 40 + ni * 8 + brow;
            u32 bh[2];
            ldmat_x2(bh, Bh + nr * LDT + k2b + bcol);
            #pragma unroll
            for (int mi = 0; mi < 4; ++mi)
                mma16816h(acc[mi][ni], ah[mi], bh);
        }
    }
}

// B fill via cp.async (160 rows x 64B = 640 chunks); B sits at offset aoffs in buf
__device__ __forceinline__ void cpB1(u32* buf, long aoffs, int t, const u16* bh,
                                     long rs, long colbase, int rows_valid) {
    #pragma unroll
    for (int ii = 0; ii < 3; ++ii) {
        int i = t + 256 * ii;
        if (i < 640) {
            int row = i >> 2, q = i & 3;
            int rc = row < rows_valid ? row : rows_valid - 1;
            const u16* s = bh + (long)rc * rs + colbase + q * 8;
            char* d = (char*)(buf + aoffs) + row * 80 + q * 16;
            cpa16(d, s, row < rows_valid ? 16u : 0u);
        }
    }
}

// ===========================================================================
// GEMM1: D[n=128,k=160] = x^T·cls ; manual A (emits xh), cp.async B (cls).
// ===========================================================================
__device__ __forceinline__ void g1_storeA(u32* buf, int n, int half, const float* pxa,
                                          u16* xh, long gbase) {
    u32 hvs[8];
    #pragma unroll
    for (int j = 0; j < 8; ++j) hvs[j] = pack2h(pxa[2 * j], pxa[2 * j + 1]);
    u32* a = buf + n * LDT + half * 8;
    *(uint4*)(a)     = make_uint4(hvs[0], hvs[1], hvs[2], hvs[3]);
    *(uint4*)(a + 4) = make_uint4(hvs[4], hvs[5], hvs[6], hvs[7]);
    #pragma unroll
    for (int j = 0; j < 8; ++j) {
        long o = gbase + (long)(2 * j) * HW;
        xh[o]      = (u16)(hvs[j] & 0xFFFF);
        xh[o + HW] = (u16)(hvs[j] >> 16);
    }
}

__global__ __launch_bounds__(256) void k_gemm1_mma(
    const float* __restrict__ x, const u16* __restrict__ clsh,
    u16* __restrict__ Eh, u16* __restrict__ xh,
    float* __restrict__ colinv, float* __restrict__ rowpart)
{
    extern __shared__ u32 sm[];
    float* srow  = (float*)(sm + 2 * BUF_N);
    float* skrow = srow + 128;
    const int t = threadIdx.x;
    const int wid = t >> 5, lane = t & 31, g = lane >> 2, tid = lane & 3;
    const int wm = wid >> 2, wn = wid & 3;
    const int n0 = blockIdx.x * 128, b = blockIdx.y;
    if (t < 128) srow[t] = 0.f;
    if (t < KPAD) skrow[t] = 0.f;

    float acc[4][5][4] = {};
    const int n = t & 127, half = t >> 7;
    const float* xb = x + (long)b * C * HW + n0 + n;

    float pxa[16];
    #pragma unroll
    for (int j = 0; j < 8; ++j) {
        int c = (half * 8 + j) * 2;
        pxa[2 * j] = xb[(long)c * HW]; pxa[2 * j + 1] = xb[(long)(c + 1) * HW];
    }
    g1_storeA(sm, n, half, pxa, xh, ((long)b * C + half * 16) * HW + n0 + n);
    cpB1(sm, SA, t, clsh, C, 0, KPAD);
    CP_COMMIT(); CP_WAIT0();
    __syncthreads();

    #pragma unroll 1
    for (int cc = 0; cc < C / KC; ++cc) {
        if (cc + 1 < C / KC) {
            #pragma unroll
            for (int j = 0; j < 8; ++j) {
                int c = (cc + 1) * KC + (half * 8 + j) * 2;
                pxa[2 * j] = xb[(long)c * HW]; pxa[2 * j + 1] = xb[(long)(c + 1) * HW];
            }
            u32* nb = sm + ((cc + 1) & 1) * BUF_N;
            cpB1(nb, SA, t, clsh, C, (cc + 1) * 32, KPAD);
            CP_COMMIT();
        }
        u32* cb_ = sm + (cc & 1) * BUF_N;
        tile_mma(cb_, cb_ + SA, acc, wm, wn, lane);
        if (cc + 1 < C / KC) {
            u32* nb = sm + ((cc + 1) & 1) * BUF_N;
            g1_storeA(nb, n, half, pxa, xh,
                      ((long)b * C + (cc + 1) * 32 + half * 16) * HW + n0 + n);
            CP_WAIT0();
            __syncthreads();
        }
    }

    #pragma unroll
    for (int mi = 0; mi < 4; ++mi) {
        const int r0 = wm * 64 + mi * 16 + g;
        float s0 = 0.f, s1 = 0.f;
        #pragma unroll
        for (int ni = 0; ni < 5; ++ni) {
            const int cb = wn * 40 + ni * 8 + tid * 2;
            float e0 = __expf(acc[mi][ni][0]);
            float e1 = __expf(acc[mi][ni][1]);
            float e2 = __expf(acc[mi][ni][2]);
            float e3 = __expf(acc[mi][ni][3]);
            float vk0 = 0.f, vk1 = 0.f;
            if (cb < KCLS) {
                long o0 = ((long)b * KCLS + cb) * HW + n0 + r0;
                Eh[o0]     = __half_as_ushort(__float2half_rn(e0));
                Eh[o0 + 8] = __half_as_ushort(__float2half_rn(e2));
                s0 += e0; s1 += e2; vk0 = e0 + e2;
            }
            if (cb + 1 < KCLS) {
                long o1 = ((long)b * KCLS + cb + 1) * HW + n0 + r0;
                Eh[o1]     = __half_as_ushort(__float2half_rn(e1));
                Eh[o1 + 8] = __half_as_ushort(__float2half_rn(e3));
                s0 += e1; s1 += e3; vk1 = e1 + e3;
            }
            vk0 += __shfl_xor_sync(0xFFFFFFFFu, vk0, 4);
            vk0 += __shfl_xor_sync(0xFFFFFFFFu, vk0, 8);
            vk0 += __shfl_xor_sync(0xFFFFFFFFu, vk0, 16);
            vk1 += __shfl_xor_sync(0xFFFFFFFFu, vk1, 4);
            vk1 += __shfl_xor_sync(0xFFFFFFFFu, vk1, 8);
            vk1 += __shfl_xor_sync(0xFFFFFFFFu, vk1, 16);
            if (g == 0 && cb < KCLS) {
                atomicAdd(&skrow[cb], vk0);
                if (cb + 1 < KCLS) atomicAdd(&skrow[cb + 1], vk1);
            }
        }
        atomicAdd(&srow[r0], s0);
        atomicAdd(&srow[r0 + 8], s1);
    }
    __syncthreads();
    if (t < 128) colinv[(long)b * HW + n0 + t] = 1.f / srow[t];
    if (t < KPAD)
        rowpart[((long)b * KPAD + t) * (HW / 128) + blockIdx.x] = skrow[t];
}

// ===========================================================================
// pool: D[c=128,k=160] = sum_n x[c,n]*E[k,n] — double-buffered cp.async.
// ===========================================================================
__device__ __forceinline__ void pool_fill(u32* buf, int t, int b, int c0, int nb,
                                          const u16* xh, const u16* Eh) {
    #pragma unroll
    for (int ii = 0; ii < 2; ++ii) {
        int i = t + 256 * ii;          // 0..511 : A = x (128 rows x 4 chunks)
        int row = i >> 2, q = i & 3;
        const u16* s = xh + ((long)b * C + c0 + row) * HW + nb + q * 8;
        char* d = (char*)buf + row * 80 + q * 16;
        cpa16(d, s, 16);
    }
    #pragma unroll
    for (int ii = 0; ii < 3; ++ii) {
        int i = t + 256 * ii;
        if (i < 640) {
            int row = i >> 2, q = i & 3;
            int rc = row < KCLS ? row : KCLS - 1;
            const u16* s = Eh + ((long)b * KCLS + rc) * HW + nb + q * 8;
            char* d = (char*)(buf + SA) + row * 80 + q * 16;
            cpa16(d, s, row < KCLS ? 16u : 0u);
        }
    }
}

__global__ __launch_bounds__(256, 2) void k_pool_mma(
    const u16* __restrict__ xh, const u16* __restrict__ Eh,
    float* __restrict__ poolpart)
{
    extern __shared__ u32 sm[];
    const int t = threadIdx.x;
    const int wid = t >> 5, lane = t & 31, g = lane >> 2, tid = lane & 3;
    const int wm = wid >> 2, wn = wid & 3;
    const int c0 = blockIdx.x * 128, sp = blockIdx.y, b = blockIdx.z;
    const int nbase = sp * (HW / NSPLIT);
    const int NCH = (HW / NSPLIT) / KC;
    float acc[4][5][4] = {};

    pool_fill(sm, t, b, c0, nbase, xh, Eh);
    CP_COMMIT(); CP_WAIT0();
    __syncthreads();

    #pragma unroll 1
    for (int cc = 0; cc < NCH; ++cc) {
        if (cc + 1 < NCH) {
            pool_fill(sm + ((cc + 1) & 1) * BUF_N, t, b, c0, nbase + (cc + 1) * KC,
                      xh, Eh);
            CP_COMMIT();
        }
        u32* cb_ = sm + (cc & 1) * BUF_N;
        tile_mma(cb_, cb_ + SA, acc, wm, wn, lane);
        if (cc + 1 < NCH) { CP_WAIT0(); __syncthreads(); }
    }

    const long base = ((long)sp * BATCH + b) * KCLS;
    #pragma unroll
    for (int mi = 0; mi < 4; ++mi) {
        const int r0 = wm * 64 + mi * 16 + g;
        #pragma unroll
        for (int ni = 0; ni < 5; ++ni) {
            const int cb = wn * 40 + ni * 8 + tid * 2;
            if (cb < KCLS) {
                poolpart[(base + cb) * C + c0 + r0]     = acc[mi][ni][0];
                poolpart[(base + cb) * C + c0 + r0 + 8] = acc[mi][ni][2];
            }
            if (cb + 1 < KCLS) {
                poolpart[(base + cb + 1) * C + c0 + r0]     = acc[mi][ni][1];
                poolpart[(base + cb + 1) * C + c0 + r0 + 8] = acc[mi][ni][3];
            }
        }
    }
}

// ===========================================================================
// masks: phase2 (E·G) first, scale by ci, then phase1 (x^T·acls); LN epilogue.
// Double-buffered cp.async.
// ===========================================================================
__device__ __forceinline__ void masks_fillA(u32* buf, int t, const u16* ah_,
                                            long rowbase, long rowlimit, long stride,
                                            long colbase) {
    #pragma unroll
    for (int ii = 0; ii < 2; ++ii) {
        int i = t + 256 * ii;          // 0..511 : 32 rows x 16 chunks
        int row = i >> 4, q = i & 15;
        long r = rowbase + row;
        long rc = r < rowlimit ? r : rowlimit - 1;
        const u16* s = ah_ + rc * stride + colbase + q * 8;
        char* d = (char*)buf + row * (LDTT * 4) + q * 16;
        cpa16(d, s, r < rowlimit ? 16u : 0u);
    }
}

__global__ __launch_bounds__(256, 2) void k_masks_mma(
    const u16* __restrict__ xh, const u16* __restrict__ aclsh,
    const u16* __restrict__ Gh, const u16* __restrict__ Eh,
    const float* __restrict__ colinv,
    const float* __restrict__ gamma, const float* __restrict__ beta,
    float* __restrict__ out)
{
    extern __shared__ u32 sm[];
    float* ssum = (float*)(sm + 2 * BUF_T);
    float* ssq  = ssum + 128;
    float* civ  = ssq + 128;
    const int t = threadIdx.x;
    const int wid = t >> 5, lane = t & 31, g = lane >> 2, tid = lane & 3;
    const int wm = wid >> 2, wn = wid & 3;
    const int n0 = blockIdx.x * 128, b = blockIdx.y;
    if (t < 128) {
        ssum[t] = 0.f; ssq[t] = 0.f;
        civ[t] = colinv[(long)b * HW + n0 + t];
    }

    float acc[4][5][4] = {};
    const u16* ab_h = aclsh + (long)b * KPAD * C;
    const u16* gb_h = Gh + (long)b * KPAD * KP2;
    const long eb = (long)b * KCLS;
    const long xbge = (long)b * C;
    const int NCH2 = KP2 / KC;          // 6 (phase 2 first)
    const int NCH  = NCH2 + C / KC;     // 22

    masks_fillA(sm, t, Eh, eb, eb + KCLS, HW, n0);
    cpB1(sm, SAT, t, gb_h, KP2, 0, KPAD);
    CP_COMMIT(); CP_WAIT0();
    __syncthreads();

    #pragma unroll 1
    for (int j = 0; j < NCH; ++j) {
        const int jn = j + 1;
        if (jn < NCH) {
            u32* nb = sm + (jn & 1) * BUF_T;
            if (jn < NCH2) {
                masks_fillA(nb, t, Eh, eb + jn * 32, eb + KCLS, HW, n0);
                cpB1(nb, SAT, t, gb_h, KP2, jn * 32, KPAD);
            } else {
                const int cc = jn - NCH2;
                masks_fillA(nb, t, xh, xbge + cc * 32, xbge + C, HW, n0);
                cpB1(nb, SAT, t, ab_h, C, cc * 32, KPAD);
            }
            CP_COMMIT();
        }
        u32* cb_ = sm + (j & 1) * BUF_T;
        tile_mma_t(cb_, cb_ + SAT, acc, wm, wn, lane);
        if (j == NCH2 - 1) {
            #pragma unroll
            for (int mi = 0; mi < 4; ++mi) {
                const int r0 = wm * 64 + mi * 16 + g;
                const float c0v = civ[r0], c1v = civ[r0 + 8];
                #pragma unroll
                for (int ni = 0; ni < 5; ++ni) {
                    acc[mi][ni][0] *= c0v; acc[mi][ni][1] *= c0v;
                    acc[mi][ni][2] *= c1v; acc[mi][ni][3] *= c1v;
                }
            }
        }
        if (jn < NCH) { CP_WAIT0(); __syncthreads(); }
    }

    // LayerNorm over k (<150)
    #pragma unroll
    for (int mi = 0; mi < 4; ++mi) {
        const int r0 = wm * 64 + mi * 16 + g;
        float s0 = 0.f, q0 = 0.f, s1 = 0.f, q1 = 0.f;
        #pragma unroll
        for (int ni = 0; ni < 5; ++ni) {
            const int cb = wn * 40 + ni * 8 + tid * 2;
            if (cb < KCLS) {
                float v = acc[mi][ni][0]; s0 += v; q0 += v * v;
                v = acc[mi][ni][2]; s1 += v; q1 += v * v;
            }
            if (cb + 1 < KCLS) {
                float v = acc[mi][ni][1]; s0 += v; q0 += v * v;
                v = acc[mi][ni][3]; s1 += v; q1 += v * v;
            }
        }
        atomicAdd(&ssum[r0], s0); atomicAdd(&ssq[r0], q0);
        atomicAdd(&ssum[r0 + 8], s1); atomicAdd(&ssq[r0 + 8], q1);
    }
    __syncthreads();
    #pragma unroll
    for (int mi = 0; mi < 4; ++mi) {
        const int r0 = wm * 64 + mi * 16 + g;
        const float mu0 = ssum[r0] * (1.f / KCLS);
        const float rs0 = rsqrtf(ssq[r0] * (1.f / KCLS) - mu0 * mu0 + 1e-5f);
        const float mu1 = ssum[r0 + 8] * (1.f / KCLS);
        const float rs1 = rsqrtf(ssq[r0 + 8] * (1.f / KCLS) - mu1 * mu1 + 1e-5f);
        #pragma unroll
        for (int ni = 0; ni < 5; ++ni) {
            const int cb = wn * 40 + ni * 8 + tid * 2;
            if (cb < KCLS) {
                float ga = gamma[cb], be = beta[cb];
                out[((long)b * KCLS + cb) * HW + n0 + r0] =
                    (acc[mi][ni][0] - mu0) * rs0 * ga + be;
                out[((long)b * KCLS + cb) * HW + n0 + r0 + 8] =
                    (acc[mi][ni][2] - mu1) * rs1 * ga + be;
            }
            if (cb + 1 < KCLS) {
                float ga = gamma[cb + 1], be = beta[cb + 1];
                out[((long)b * KCLS + cb + 1) * HW + n0 + r0] =
                    (acc[mi][ni][1] - mu0) * rs0 * ga + be;
                out[((long)b * KCLS + cb + 1) * HW + n0 + r0 + 8] =
                    (acc[mi][ni][3] - mu1) * rs1 * ga + be;
            }
        }
    }
}

// ===========================================================================
// SIMT small kernels
// ===========================================================================
__global__ void k_prep(const float* __restrict__ cls, u16* __restrict__ ch_)
{
    int i = blockIdx.x * 256 + threadIdx.x;
    if (i < KPAD * C) {
        float v = (i < KCLS * C) ? cls[i] : 0.f;
        ch_[i] = __half_as_ushort(__float2half_rn(v));
    }
}

__global__ void k_rowred(const float* __restrict__ rowpart, float* __restrict__ rinv)
{
    int idx = blockIdx.x * 256 + threadIdx.x;
    if (idx < BATCH * KPAD) {
        const float* p = rowpart + (long)idx * (HW / 128);
        float s = 0.f;
        for (int i = 0; i < HW / 128; ++i) s += p[i];
        rinv[idx] = 1.f / s;
    }
}

// bounded-K small GEMM body
__device__ __forceinline__ void sg_body(
    const float* __restrict__ A, int arow_valid, const float* __restrict__ W, int brow_valid,
    float acc[4][4], int t, float As[16][64], float Bs[16][64], int pbeg, int pend)
{
    const int tm = (t >> 4) * 4, tn = (t & 15) * 4;
    const int ar = t >> 2, ac = (t & 3) * 4;
    const int bc = t >> 2, bp = (t & 3) * 4;
    for (int p0 = pbeg; p0 < pend; p0 += 16) {
        float4 av = make_float4(0.f, 0.f, 0.f, 0.f);
        if (ar < arow_valid) av = *(const float4*)&A[(long)ar * C + p0 + ac];
        As[ac + 0][ar] = av.x; As[ac + 1][ar] = av.y; As[ac + 2][ar] = av.z; As[ac + 3][ar] = av.w;
        float4 bv = make_float4(0.f, 0.f, 0.f, 0.f);
        if (bc < brow_valid) bv = *(const float4*)&W[(long)bc * C + p0 + bp];
        Bs[bp + 0][bc] = bv.x; Bs[bp + 1][bc] = bv.y; Bs[bp + 2][bc] = bv.z; Bs[bp + 3][bc] = bv.w;
        __syncthreads();
        #pragma unroll
        for (int kk = 0; kk < 16; ++kk) {
            float4 a4 = *(const float4*)&As[kk][tm];
            float4 b4 = *(const float4*)&Bs[kk][tn];
            float aa[4] = {a4.x, a4.y, a4.z, a4.w};
            float bb[4] = {b4.x, b4.y, b4.z, b4.w};
            #pragma unroll
            for (int i = 0; i < 4; ++i)
                #pragma unroll
                for (int j = 0; j < 4; ++j)
                    acc[i][j] = fmaf(aa[i], bb[j], acc[i][j]);
        }
        __syncthreads();
    }
}

// clsWf split-K partials: grid (3, 8, 4)
__global__ __launch_bounds__(256) void k_clsWf(
    const float* __restrict__ cls, const float* __restrict__ W, float* __restrict__ outp)
{
    __shared__ float As[16][64], Bs[16][64];
    const int t = threadIdx.x, k0 = blockIdx.x * 64, c0 = blockIdx.y * 64;
    const int z = blockIdx.z;
    float acc[4][4] = {};
    int av = KCLS - k0; av = av > 64 ? 64 : (av > 0 ? av : 0);
    sg_body(cls + (long)k0 * C, av, W + (long)c0 * C, 64, acc, t, As, Bs,
            z * 128, z * 128 + 128);
    const int tm = (t >> 4) * 4, tn = (t & 15) * 4;
    #pragma unroll
    for (int i = 0; i < 4; ++i) {
        int k = k0 + tm + i;
        if (k < KCLS)
            *(float4*)&outp[(long)z * KCLS * C + (long)k * C + c0 + tn] =
                make_float4(acc[i][0], acc[i][1], acc[i][2], acc[i][3]);
    }
}

__global__ void k_red4(const float* __restrict__ p, float* __restrict__ o)
{
    int i = blockIdx.x * 256 + threadIdx.x;
    if (i < KCLS * C)
        o[i] = p[i] + p[KCLS * C + i] + p[2 * KCLS * C + i] + p[3 * KCLS * C + i];
}

__global__ __launch_bounds__(256) void k_acls(
    const float* __restrict__ poolpart, const float* __restrict__ rinv,
    const float* __restrict__ W, const float* __restrict__ cls,
    float* __restrict__ outf, u16* __restrict__ outh)
{
    __shared__ float As[16][64], Bs[16][64];
    const int t = threadIdx.x;
    const int k0 = blockIdx.x * 64, c0 = blockIdx.y * 64, b = blockIdx.z;
    const int tm = (t >> 4) * 4, tn = (t & 15) * 4;
    const int ar = t >> 2, ac = (t & 3) * 4;
    const int bc = t >> 2, bp = (t & 3) * 4;
    float acc[4][4] = {};
    const int ka = k0 + ar;
    const float rv = (ka < KCLS) ? rinv[b * KPAD + ka] : 0.f;

    for (int p0 = 0; p0 < C; p0 += 16) {
        float4 av = make_float4(0.f, 0.f, 0.f, 0.f);
        if (ka < KCLS) {
            #pragma unroll
            for (int s = 0; s < NSPLIT; ++s) {
                float4 v = *(const float4*)
                    &poolpart[(((long)s * BATCH + b) * KCLS + ka) * C + p0 + ac];
                av.x += v.x; av.y += v.y; av.z += v.z; av.w += v.w;
            }
            av.x *= rv; av.y *= rv; av.z *= rv; av.w *= rv;
        }
        As[ac + 0][ar] = av.x; As[ac + 1][ar] = av.y; As[ac + 2][ar] = av.z; As[ac + 3][ar] = av.w;
        float4 bv = *(const float4*)&W[(long)(c0 + bc) * C + p0 + bp];
        Bs[bp + 0][bc] = bv.x; Bs[bp + 1][bc] = bv.y; Bs[bp + 2][bc] = bv.z; Bs[bp + 3][bc] = bv.w;
        __syncthreads();
        #pragma unroll
        for (int kk = 0; kk < 16; ++kk) {
            float4 a4 = *(const float4*)&As[kk][tm];
            float4 b4 = *(const float4*)&Bs[kk][tn];
            float aa[4] = {a4.x, a4.y, a4.z, a4.w};
            float bb[4] = {b4.x, b4.y, b4.z, b4.w};
            #pragma unroll
            for (int i = 0; i < 4; ++i)
                #pragma unroll
                for (int j = 0; j < 4; ++j)
                    acc[i][j] = fmaf(aa[i], bb[j], acc[i][j]);
        }
        __syncthreads();
    }
    #pragma unroll
    for (int i = 0; i < 4; ++i) {
        int k = k0 + tm + i;
        if (k < KCLS) {
            #pragma unroll
            for (int j = 0; j < 4; ++j) {
                float v = acc[i][j] + cls[(long)k * C + c0 + tn + j];
                outf[((long)b * KCLS + k) * C + c0 + tn + j] = v;
                outh[((long)b * KPAD + k) * C + c0 + tn + j] =
                    __half_as_ushort(__float2half_rn(v));
            }
        } else if (k < KPAD) {
            #pragma unroll
            for (int j = 0; j < 4; ++j)
                outh[((long)b * KPAD + k) * C + c0 + tn + j] = 0;
        }
    }
}

__global__ __launch_bounds__(256) void k_G(
    const float* __restrict__ acls, const float* __restrict__ clsWf,
    u16* __restrict__ Gh)
{
    __shared__ float As[16][64], Bs[16][64];
    const int t = threadIdx.x;
    const int k0 = blockIdx.x * 64, k20 = blockIdx.y * 64, b = blockIdx.z;
    float acc[4][4] = {};
    int av = KCLS - k0; av = av > 64 ? 64 : (av > 0 ? av : 0);
    int bv = KCLS - k20; bv = bv > 64 ? 64 : (bv > 0 ? bv : 0);
    sg_body(acls + ((long)b * KCLS + k0) * C, av, clsWf + (long)k20 * C, bv,
            acc, t, As, Bs, 0, C);
    const int tm = (t >> 4) * 4, tn = (t & 15) * 4;
    #pragma unroll
    for (int i = 0; i < 4; ++i) {
        int k = k0 + tm + i;
        if (k < KPAD) {
            #pragma unroll
            for (int j = 0; j < 4; ++j)
                Gh[((long)b * KPAD + k) * KP2 + k20 + tn + j] =
                    __half_as_ushort(__float2half_rn(acc[i][j]));
        }
    }
}

// ===========================================================================
extern "C" void kernel_launch(void* const* d_in, const int* in_sizes, int n_in,
                              void* d_out, int out_size)
{
    const float* x     = (const float*)d_in[0];
    const float* cls   = (const float*)d_in[1];
    const float* Wcls  = (const float*)d_in[2];
    const float* Wfeat = (const float*)d_in[3];
    const float* gamma = (const float*)d_in[4];
    const float* beta  = (const float*)d_in[5];
    float* out = (float*)d_out;

    u16 *clsh, *aclsh, *Gh, *Eh, *xh;
    float *colinv, *rowpart, *rinv, *poolpart, *acls, *clsWfp, *clsWf;
    cudaGetSymbolAddress((void**)&clsh,  g_clsh);
    cudaGetSymbolAddress((void**)&Eh,    g_Eh);
    cudaGetSymbolAddress((void**)&xh,    g_xh);
    cudaGetSymbolAddress((void**)&colinv, g_colinv);
    cudaGetSymbolAddress((void**)&rowpart, g_rowpart);
    cudaGetSymbolAddress((void**)&rinv,  g_rinv);
    cudaGetSymbolAddress((void**)&poolpart, g_poolpart);
    cudaGetSymbolAddress((void**)&acls,  g_acls);
    cudaGetSymbolAddress((void**)&aclsh, g_aclsh);
    cudaGetSymbolAddress((void**)&clsWfp, g_clsWfp);
    cudaGetSymbolAddress((void**)&clsWf, g_clsWf);
    cudaGetSymbolAddress((void**)&Gh,    g_Gh);

    cudaFuncSetAttribute(k_gemm1_mma, cudaFuncAttributeMaxDynamicSharedMemorySize, SMEM_N);
    cudaFuncSetAttribute(k_pool_mma,  cudaFuncAttributeMaxDynamicSharedMemorySize, SMEM_N);
    cudaFuncSetAttribute(k_masks_mma, cudaFuncAttributeMaxDynamicSharedMemorySize, SMEM_T);

    k_prep<<<(KPAD * C + 255) / 256, 256>>>(cls, clsh);
    k_gemm1_mma<<<dim3(HW / 128, BATCH), 256, SMEM_N>>>(
        x, clsh, Eh, xh, colinv, rowpart);
    k_rowred<<<(BATCH * KPAD + 255) / 256, 256>>>(rowpart, rinv);
    k_pool_mma<<<dim3(C / 128, NSPLIT, BATCH), 256, SMEM_N>>>(xh, Eh, poolpart);
    k_clsWf<<<dim3(3, C / 64, 4), 256>>>(cls, Wfeat, clsWfp);
    k_red4<<<(KCLS * C + 255) / 256, 256>>>(clsWfp, clsWf);
    k_acls<<<dim3(3, C / 64, BATCH), 256>>>(poolpart, rinv, Wcls, cls, acls, aclsh);
    k_G<<<dim3(3, 3, BATCH), 256>>>(acls, clsWf, Gh);
    k_masks_mma<<<dim3(HW / 128, BATCH), 256, SMEM_T>>>(
        xh, aclsh, Gh, Eh, colinv, gamma, beta, out);
}

// round 15
// speedup vs baseline: 1.4741x; 1.0593x over previous
#include <cuda_runtime.h>
#include <cuda_fp16.h>
#include <stdint.h>

#define BATCH 8
#define C 512
#define HW 16384
#define KCLS 150
#define KPAD 160
#define KP2 192
#define NSPLIT 16
#define KC 32
#define LDT 20             // u32 row stride, non-trans tiles
#define LDTT 68            // u32 row stride, trans (K-major) A tiles
#define SA (128 * LDT)
#define SB (KPAD * LDT)
#define SAT (32 * LDTT)
#define BUF_N (SA + SB)            // gemm1 / pool buffer (u32): A, B
#define BUF_T (SAT + SB)           // masks buffer (u32)
#define SMEM_N (2 * BUF_N * 4 + 2048)
#define SMEM_T (2 * BUF_T * 4 + 2048)

typedef unsigned int u32;
typedef unsigned short u16;

// ---------------- scratch (device globals; no allocations) ----------------
__device__ u16  g_clsh[KPAD * C];                 // cls fp16 (zero-padded rows)
__device__ u16  g_xh[(long)BATCH * C * HW];       // x fp16
__device__ u16  g_Eh[(long)BATCH * KCLS * HW];    // E fp16
__device__ float g_colinv[BATCH * HW];
__device__ float g_rowpart[(long)BATCH * KPAD * (HW / 128)];
__device__ float g_rinv[BATCH * KPAD];
__device__ float g_poolpart[(long)NSPLIT * BATCH * KCLS * C];
__device__ float g_pool[BATCH * KCLS * C];        // reduced + rinv-scaled
__device__ float g_acls[BATCH * KCLS * C];
__device__ u16  g_aclsh[BATCH * KPAD * C];        // acls fp16 (zero-padded)
__device__ float g_clsWfp[4 * KCLS * C];          // split-K partials
__device__ float g_clsWf[KCLS * C];
__device__ u16  g_Gh[BATCH * KPAD * KP2];         // G fp16

// ---------------- helpers ----------------
__device__ __forceinline__ u32 pack2h(float v0, float v1) {
    return (u32)__half_as_ushort(__float2half_rn(v0)) |
           ((u32)__half_as_ushort(__float2half_rn(v1)) << 16);
}
__device__ __forceinline__ void mma16816h(float c[4], const u32 a[4], const u32 b[2]) {
    asm volatile(
        "mma.sync.aligned.m16n8k16.row.col.f32.f16.f16.f32 "
        "{%0,%1,%2,%3}, {%4,%5,%6,%7}, {%8,%9}, {%0,%1,%2,%3};"
        : "+f"(c[0]), "+f"(c[1]), "+f"(c[2]), "+f"(c[3])
        : "r"(a[0]), "r"(a[1]), "r"(a[2]), "r"(a[3]), "r"(b[0]), "r"(b[1]));
}
__device__ __forceinline__ void ldmat_x4(u32 r[4], const void* p) {
    u32 a = (u32)__cvta_generic_to_shared(p);
    asm volatile("ldmatrix.sync.aligned.m8n8.x4.shared.b16 {%0,%1,%2,%3}, [%4];"
                 : "=r"(r[0]), "=r"(r[1]), "=r"(r[2]), "=r"(r[3]) : "r"(a));
}
__device__ __forceinline__ void ldmat_x4t(u32 r[4], const void* p) {
    u32 a = (u32)__cvta_generic_to_shared(p);
    asm volatile("ldmatrix.sync.aligned.m8n8.x4.trans.shared.b16 {%0,%1,%2,%3}, [%4];"
                 : "=r"(r[0]), "=r"(r[1]), "=r"(r[2]), "=r"(r[3]) : "r"(a));
}
__device__ __forceinline__ void ldmat_x2(u32 r[2], const void* p) {
    u32 a = (u32)__cvta_generic_to_shared(p);
    asm volatile("ldmatrix.sync.aligned.m8n8.x2.shared.b16 {%0,%1}, [%2];"
                 : "=r"(r[0]), "=r"(r[1]) : "r"(a));
}
__device__ __forceinline__ void cpa16(void* dst, const void* src, u32 srcsz) {
    u32 d = (u32)__cvta_generic_to_shared(dst);
    asm volatile("cp.async.cg.shared.global [%0], [%1], 16, %2;"
                 :: "r"(d), "l"(src), "r"(srcsz) : "memory");
}
#define CP_COMMIT() asm volatile("cp.async.commit_group;" ::: "memory")
#define CP_WAIT0()  asm volatile("cp.async.wait_group 0;" ::: "memory")

// ---- MMA cores (single fp16 term) -----------------------------------------
__device__ __forceinline__ void tile_mma(
    const u32* Ah, const u32* Bh, float (*acc)[5][4], int wm, int wn, int lane)
{
    const int arow = lane & 15, acol = (lane >> 4) << 2;
    const int brow = lane & 7,  bcol = ((lane >> 3) & 1) << 2;
    #pragma unroll
    for (int ks = 0; ks < 2; ++ks) {
        const int k2b = ks * 8;
        u32 ah[4][4];
        #pragma unroll
        for (int mi = 0; mi < 4; ++mi) {
            const int r = wm * 64 + mi * 16 + arow;
            ldmat_x4(ah[mi], Ah + r * LDT + k2b + acol);
        }
        #pragma unroll
        for (int ni = 0; ni < 5; ++ni) {
            const int nr = wn * 40 + ni * 8 + brow;
            u32 bh[2];
            ldmat_x2(bh, Bh + nr * LDT + k2b + bcol);
            #pragma unroll
            for (int mi = 0; mi < 4; ++mi)
                mma16816h(acc[mi][ni], ah[mi], bh);
        }
    }
}
// trans A: smem [K=32 rows][M=128 u16 cols], stride LDTT
__device__ __forceinline__ void tile_mma_t(
    const u32* Ah, const u32* Bh, float (*acc)[5][4], int wm, int wn, int lane)
{
    const int kr = (lane & 7) + ((lane >> 4) << 3);
    const int mo = ((lane >> 3) & 1) << 3;
    const int brow = lane & 7, bcol = ((lane >> 3) & 1) << 2;
    #pragma unroll
    for (int ks = 0; ks < 2; ++ks) {
        const int k2b = ks * 8;
        u32 ah[4][4];
        #pragma unroll
        for (int mi = 0; mi < 4; ++mi) {
            const int m = wm * 64 + mi * 16 + mo;
            ldmat_x4t(ah[mi], (const u16*)(Ah + (ks * 16 + kr) * LDTT) + m);
        }
        #pragma unroll
        for (int ni = 0; ni < 5; ++ni) {
            const int nr = wn * 40 + ni * 8 + brow;
            u32 bh[2];
            ldmat_x2(bh, Bh + nr * LDT + k2b + bcol);
            #pragma unroll
            for (int mi = 0; mi < 4; ++mi)
                mma16816h(acc[mi][ni], ah[mi], bh);
        }
    }
}

// B fill via cp.async (160 rows x 64B = 640 chunks); B sits at offset aoffs in buf
__device__ __forceinline__ void cpB1(u32* buf, long aoffs, int t, const u16* bh,
                                     long rs, long colbase, int rows_valid) {
    #pragma unroll
    for (int ii = 0; ii < 3; ++ii) {
        int i = t + 256 * ii;
        if (i < 640) {
            int row = i >> 2, q = i & 3;
            int rc = row < rows_valid ? row : rows_valid - 1;
            const u16* s = bh + (long)rc * rs + colbase + q * 8;
            char* d = (char*)(buf + aoffs) + row * 80 + q * 16;
            cpa16(d, s, row < rows_valid ? 16u : 0u);
        }
    }
}

// ===========================================================================
// GEMM1: D[n=128,k=160] = x^T·cls ; manual A (emits xh), cp.async B (cls).
// ===========================================================================
__device__ __forceinline__ void g1_storeA(u32* buf, int n, int half, const float* pxa,
                                          u16* xh, long gbase) {
    u32 hvs[8];
    #pragma unroll
    for (int j = 0; j < 8; ++j) hvs[j] = pack2h(pxa[2 * j], pxa[2 * j + 1]);
    u32* a = buf + n * LDT + half * 8;
    *(uint4*)(a)     = make_uint4(hvs[0], hvs[1], hvs[2], hvs[3]);
    *(uint4*)(a + 4) = make_uint4(hvs[4], hvs[5], hvs[6], hvs[7]);
    #pragma unroll
    for (int j = 0; j < 8; ++j) {
        long o = gbase + (long)(2 * j) * HW;
        xh[o]      = (u16)(hvs[j] & 0xFFFF);
        xh[o + HW] = (u16)(hvs[j] >> 16);
    }
}

__global__ __launch_bounds__(256) void k_gemm1_mma(
    const float* __restrict__ x, const u16* __restrict__ clsh,
    u16* __restrict__ Eh, u16* __restrict__ xh,
    float* __restrict__ colinv, float* __restrict__ rowpart)
{
    extern __shared__ u32 sm[];
    float* srow  = (float*)(sm + 2 * BUF_N);
    float* skrow = srow + 128;
    const int t = threadIdx.x;
    const int wid = t >> 5, lane = t & 31, g = lane >> 2, tid = lane & 3;
    const int wm = wid >> 2, wn = wid & 3;
    const int n0 = blockIdx.x * 128, b = blockIdx.y;
    if (t < 128) srow[t] = 0.f;
    if (t < KPAD) skrow[t] = 0.f;

    float acc[4][5][4] = {};
    const int n = t & 127, half = t >> 7;
    const float* xb = x + (long)b * C * HW + n0 + n;

    float pxa[16];
    #pragma unroll
    for (int j = 0; j < 8; ++j) {
        int c = (half * 8 + j) * 2;
        pxa[2 * j] = xb[(long)c * HW]; pxa[2 * j + 1] = xb[(long)(c + 1) * HW];
    }
    g1_storeA(sm, n, half, pxa, xh, ((long)b * C + half * 16) * HW + n0 + n);
    cpB1(sm, SA, t, clsh, C, 0, KPAD);
    CP_COMMIT(); CP_WAIT0();
    __syncthreads();

    #pragma unroll 1
    for (int cc = 0; cc < C / KC; ++cc) {
        if (cc + 1 < C / KC) {
            #pragma unroll
            for (int j = 0; j < 8; ++j) {
                int c = (cc + 1) * KC + (half * 8 + j) * 2;
                pxa[2 * j] = xb[(long)c * HW]; pxa[2 * j + 1] = xb[(long)(c + 1) * HW];
            }
            u32* nb = sm + ((cc + 1) & 1) * BUF_N;
            cpB1(nb, SA, t, clsh, C, (cc + 1) * 32, KPAD);
            CP_COMMIT();
        }
        u32* cb_ = sm + (cc & 1) * BUF_N;
        tile_mma(cb_, cb_ + SA, acc, wm, wn, lane);
        if (cc + 1 < C / KC) {
            u32* nb = sm + ((cc + 1) & 1) * BUF_N;
            g1_storeA(nb, n, half, pxa, xh,
                      ((long)b * C + (cc + 1) * 32 + half * 16) * HW + n0 + n);
            CP_WAIT0();
            __syncthreads();
        }
    }

    #pragma unroll
    for (int mi = 0; mi < 4; ++mi) {
        const int r0 = wm * 64 + mi * 16 + g;
        float s0 = 0.f, s1 = 0.f;
        #pragma unroll
        for (int ni = 0; ni < 5; ++ni) {
            const int cb = wn * 40 + ni * 8 + tid * 2;
            float e0 = __expf(acc[mi][ni][0]);
            float e1 = __expf(acc[mi][ni][1]);
            float e2 = __expf(acc[mi][ni][2]);
            float e3 = __expf(acc[mi][ni][3]);
            float vk0 = 0.f, vk1 = 0.f;
            if (cb < KCLS) {
                long o0 = ((long)b * KCLS + cb) * HW + n0 + r0;
                Eh[o0]     = __half_as_ushort(__float2half_rn(e0));
                Eh[o0 + 8] = __half_as_ushort(__float2half_rn(e2));
                s0 += e0; s1 += e2; vk0 = e0 + e2;
            }
            if (cb + 1 < KCLS) {
                long o1 = ((long)b * KCLS + cb + 1) * HW + n0 + r0;
                Eh[o1]     = __half_as_ushort(__float2half_rn(e1));
                Eh[o1 + 8] = __half_as_ushort(__float2half_rn(e3));
                s0 += e1; s1 += e3; vk1 = e1 + e3;
            }
            vk0 += __shfl_xor_sync(0xFFFFFFFFu, vk0, 4);
            vk0 += __shfl_xor_sync(0xFFFFFFFFu, vk0, 8);
            vk0 += __shfl_xor_sync(0xFFFFFFFFu, vk0, 16);
            vk1 += __shfl_xor_sync(0xFFFFFFFFu, vk1, 4);
            vk1 += __shfl_xor_sync(0xFFFFFFFFu, vk1, 8);
            vk1 += __shfl_xor_sync(0xFFFFFFFFu, vk1, 16);
            if (g == 0 && cb < KCLS) {
                atomicAdd(&skrow[cb], vk0);
                if (cb + 1 < KCLS) atomicAdd(&skrow[cb + 1], vk1);
            }
        }
        atomicAdd(&srow[r0], s0);
        atomicAdd(&srow[r0 + 8], s1);
    }
    __syncthreads();
    if (t < 128) colinv[(long)b * HW + n0 + t] = 1.f / srow[t];
    if (t < KPAD)
        rowpart[((long)b * KPAD + t) * (HW / 128) + blockIdx.x] = skrow[t];
}

// ===========================================================================
// pool: D[c=128,k=160] = sum_n x[c,n]*E[k,n] — double-buffered cp.async.
// ===========================================================================
__device__ __forceinline__ void pool_fill(u32* buf, int t, int b, int c0, int nb,
                                          const u16* xh, const u16* Eh) {
    #pragma unroll
    for (int ii = 0; ii < 2; ++ii) {
        int i = t + 256 * ii;          // 0..511 : A = x (128 rows x 4 chunks)
        int row = i >> 2, q = i & 3;
        const u16* s = xh + ((long)b * C + c0 + row) * HW + nb + q * 8;
        char* d = (char*)buf + row * 80 + q * 16;
        cpa16(d, s, 16);
    }
    #pragma unroll
    for (int ii = 0; ii < 3; ++ii) {
        int i = t + 256 * ii;
        if (i < 640) {
            int row = i >> 2, q = i & 3;
            int rc = row < KCLS ? row : KCLS - 1;
            const u16* s = Eh + ((long)b * KCLS + rc) * HW + nb + q * 8;
            char* d = (char*)(buf + SA) + row * 80 + q * 16;
            cpa16(d, s, row < KCLS ? 16u : 0u);
        }
    }
}

__global__ __launch_bounds__(256, 2) void k_pool_mma(
    const u16* __restrict__ xh, const u16* __restrict__ Eh,
    float* __restrict__ poolpart)
{
    extern __shared__ u32 sm[];
    const int t = threadIdx.x;
    const int wid = t >> 5, lane = t & 31, g = lane >> 2, tid = lane & 3;
    const int wm = wid >> 2, wn = wid & 3;
    const int c0 = blockIdx.x * 128, sp = blockIdx.y, b = blockIdx.z;
    const int nbase = sp * (HW / NSPLIT);
    const int NCH = (HW / NSPLIT) / KC;
    float acc[4][5][4] = {};

    pool_fill(sm, t, b, c0, nbase, xh, Eh);
    CP_COMMIT(); CP_WAIT0();
    __syncthreads();

    #pragma unroll 1
    for (int cc = 0; cc < NCH; ++cc) {
        if (cc + 1 < NCH) {
            pool_fill(sm + ((cc + 1) & 1) * BUF_N, t, b, c0, nbase + (cc + 1) * KC,
                      xh, Eh);
            CP_COMMIT();
        }
        u32* cb_ = sm + (cc & 1) * BUF_N;
        tile_mma(cb_, cb_ + SA, acc, wm, wn, lane);
        if (cc + 1 < NCH) { CP_WAIT0(); __syncthreads(); }
    }

    const long base = ((long)sp * BATCH + b) * KCLS;
    #pragma unroll
    for (int mi = 0; mi < 4; ++mi) {
        const int r0 = wm * 64 + mi * 16 + g;
        #pragma unroll
        for (int ni = 0; ni < 5; ++ni) {
            const int cb = wn * 40 + ni * 8 + tid * 2;
            if (cb < KCLS) {
                poolpart[(base + cb) * C + c0 + r0]     = acc[mi][ni][0];
                poolpart[(base + cb) * C + c0 + r0 + 8] = acc[mi][ni][2];
            }
            if (cb + 1 < KCLS) {
                poolpart[(base + cb + 1) * C + c0 + r0]     = acc[mi][ni][1];
                poolpart[(base + cb + 1) * C + c0 + r0 + 8] = acc[mi][ni][3];
            }
        }
    }
}

// ===========================================================================
// masks: phase2 (E·G) first, scale by ci, then phase1 (x^T·acls); LN epilogue.
// ===========================================================================
__device__ __forceinline__ void masks_fillA(u32* buf, int t, const u16* ah_,
                                            long rowbase, long rowlimit, long stride,
                                            long colbase) {
    #pragma unroll
    for (int ii = 0; ii < 2; ++ii) {
        int i = t + 256 * ii;          // 0..511 : 32 rows x 16 chunks
        int row = i >> 4, q = i & 15;
        long r = rowbase + row;
        long rc = r < rowlimit ? r : rowlimit - 1;
        const u16* s = ah_ + rc * stride + colbase + q * 8;
        char* d = (char*)buf + row * (LDTT * 4) + q * 16;
        cpa16(d, s, r < rowlimit ? 16u : 0u);
    }
}

__global__ __launch_bounds__(256, 2) void k_masks_mma(
    const u16* __restrict__ xh, const u16* __restrict__ aclsh,
    const u16* __restrict__ Gh, const u16* __restrict__ Eh,
    const float* __restrict__ colinv,
    const float* __restrict__ gamma, const float* __restrict__ beta,
    float* __restrict__ out)
{
    extern __shared__ u32 sm[];
    float* ssum = (float*)(sm + 2 * BUF_T);
    float* ssq  = ssum + 128;
    float* civ  = ssq + 128;
    const int t = threadIdx.x;
    const int wid = t >> 5, lane = t & 31, g = lane >> 2, tid = lane & 3;
    const int wm = wid >> 2, wn = wid & 3;
    const int n0 = blockIdx.x * 128, b = blockIdx.y;
    if (t < 128) {
        ssum[t] = 0.f; ssq[t] = 0.f;
        civ[t] = colinv[(long)b * HW + n0 + t];
    }

    float acc[4][5][4] = {};
    const u16* ab_h = aclsh + (long)b * KPAD * C;
    const u16* gb_h = Gh + (long)b * KPAD * KP2;
    const long eb = (long)b * KCLS;
    const long xbge = (long)b * C;
    const int NCH2 = KP2 / KC;          // 6 (phase 2 first)
    const int NCH  = NCH2 + C / KC;     // 22

    masks_fillA(sm, t, Eh, eb, eb + KCLS, HW, n0);
    cpB1(sm, SAT, t, gb_h, KP2, 0, KPAD);
    CP_COMMIT(); CP_WAIT0();
    __syncthreads();

    #pragma unroll 1
    for (int j = 0; j < NCH; ++j) {
        const int jn = j + 1;
        if (jn < NCH) {
            u32* nb = sm + (jn & 1) * BUF_T;
            if (jn < NCH2) {
                masks_fillA(nb, t, Eh, eb + jn * 32, eb + KCLS, HW, n0);
                cpB1(nb, SAT, t, gb_h, KP2, jn * 32, KPAD);
            } else {
                const int cc = jn - NCH2;
                masks_fillA(nb, t, xh, xbge + cc * 32, xbge + C, HW, n0);
                cpB1(nb, SAT, t, ab_h, C, cc * 32, KPAD);
            }
            CP_COMMIT();
        }
        u32* cb_ = sm + (j & 1) * BUF_T;
        tile_mma_t(cb_, cb_ + SAT, acc, wm, wn, lane);
        if (j == NCH2 - 1) {
            #pragma unroll
            for (int mi = 0; mi < 4; ++mi) {
                const int r0 = wm * 64 + mi * 16 + g;
                const float c0v = civ[r0], c1v = civ[r0 + 8];
                #pragma unroll
                for (int ni = 0; ni < 5; ++ni) {
                    acc[mi][ni][0] *= c0v; acc[mi][ni][1] *= c0v;
                    acc[mi][ni][2] *= c1v; acc[mi][ni][3] *= c1v;
                }
            }
        }
        if (jn < NCH) { CP_WAIT0(); __syncthreads(); }
    }

    // LayerNorm over k (<150)
    #pragma unroll
    for (int mi = 0; mi < 4; ++mi) {
        const int r0 = wm * 64 + mi * 16 + g;
        float s0 = 0.f, q0 = 0.f, s1 = 0.f, q1 = 0.f;
        #pragma unroll
        for (int ni = 0; ni < 5; ++ni) {
            const int cb = wn * 40 + ni * 8 + tid * 2;
            if (cb < KCLS) {
                float v = acc[mi][ni][0]; s0 += v; q0 += v * v;
                v = acc[mi][ni][2]; s1 += v; q1 += v * v;
            }
            if (cb + 1 < KCLS) {
                float v = acc[mi][ni][1]; s0 += v; q0 += v * v;
                v = acc[mi][ni][3]; s1 += v; q1 += v * v;
            }
        }
        atomicAdd(&ssum[r0], s0); atomicAdd(&ssq[r0], q0);
        atomicAdd(&ssum[r0 + 8], s1); atomicAdd(&ssq[r0 + 8], q1);
    }
    __syncthreads();
    #pragma unroll
    for (int mi = 0; mi < 4; ++mi) {
        const int r0 = wm * 64 + mi * 16 + g;
        const float mu0 = ssum[r0] * (1.f / KCLS);
        const float rs0 = rsqrtf(ssq[r0] * (1.f / KCLS) - mu0 * mu0 + 1e-5f);
        const float mu1 = ssum[r0 + 8] * (1.f / KCLS);
        const float rs1 = rsqrtf(ssq[r0 + 8] * (1.f / KCLS) - mu1 * mu1 + 1e-5f);
        #pragma unroll
        for (int ni = 0; ni < 5; ++ni) {
            const int cb = wn * 40 + ni * 8 + tid * 2;
            if (cb < KCLS) {
                float ga = gamma[cb], be = beta[cb];
                out[((long)b * KCLS + cb) * HW + n0 + r0] =
                    (acc[mi][ni][0] - mu0) * rs0 * ga + be;
                out[((long)b * KCLS + cb) * HW + n0 + r0 + 8] =
                    (acc[mi][ni][2] - mu1) * rs1 * ga + be;
            }
            if (cb + 1 < KCLS) {
                float ga = gamma[cb + 1], be = beta[cb + 1];
                out[((long)b * KCLS + cb + 1) * HW + n0 + r0] =
                    (acc[mi][ni][1] - mu0) * rs0 * ga + be;
                out[((long)b * KCLS + cb + 1) * HW + n0 + r0 + 8] =
                    (acc[mi][ni][3] - mu1) * rs1 * ga + be;
            }
        }
    }
}

// ===========================================================================
// SIMT small kernels
// ===========================================================================
__global__ void k_prep(const float* __restrict__ cls, u16* __restrict__ ch_)
{
    int i = blockIdx.x * 256 + threadIdx.x;
    if (i < KPAD * C) {
        float v = (i < KCLS * C) ? cls[i] : 0.f;
        ch_[i] = __half_as_ushort(__float2half_rn(v));
    }
}

__global__ void k_rowred(const float* __restrict__ rowpart, float* __restrict__ rinv)
{
    int idx = blockIdx.x * 256 + threadIdx.x;
    if (idx < BATCH * KPAD) {
        const float* p = rowpart + (long)idx * (HW / 128);
        float s = 0.f;
        for (int i = 0; i < HW / 128; ++i) s += p[i];
        rinv[idx] = 1.f / s;
    }
}

// pool reduce: pool[b,k,c] = rinv[b,k] * sum_s poolpart[s,b,k,c]
__global__ void k_poolred(const float* __restrict__ poolpart,
                          const float* __restrict__ rinv, float* __restrict__ pool)
{
    long i = (long)blockIdx.x * 256 + threadIdx.x;   // b*KCLS*C + k*C + c
    if (i < (long)BATCH * KCLS * C) {
        float s = 0.f;
        #pragma unroll
        for (int sp = 0; sp < NSPLIT; ++sp)
            s += poolpart[(long)sp * BATCH * KCLS * C + i];
        int b = (int)(i / (KCLS * C));
        int k = (int)((i / C) % KCLS);
        pool[i] = s * rinv[b * KPAD + k];
    }
}

// bounded-K small GEMM body
__device__ __forceinline__ void sg_body(
    const float* __restrict__ A, int arow_valid, const float* __restrict__ W, int brow_valid,
    float acc[4][4], int t, float As[16][64], float Bs[16][64], int pbeg, int pend)
{
    const int tm = (t >> 4) * 4, tn = (t & 15) * 4;
    const int ar = t >> 2, ac = (t & 3) * 4;
    const int bc = t >> 2, bp = (t & 3) * 4;
    for (int p0 = pbeg; p0 < pend; p0 += 16) {
        float4 av = make_float4(0.f, 0.f, 0.f, 0.f);
        if (ar < arow_valid) av = *(const float4*)&A[(long)ar * C + p0 + ac];
        As[ac + 0][ar] = av.x; As[ac + 1][ar] = av.y; As[ac + 2][ar] = av.z; As[ac + 3][ar] = av.w;
        float4 bv = make_float4(0.f, 0.f, 0.f, 0.f);
        if (bc < brow_valid) bv = *(const float4*)&W[(long)bc * C + p0 + bp];
        Bs[bp + 0][bc] = bv.x; Bs[bp + 1][bc] = bv.y; Bs[bp + 2][bc] = bv.z; Bs[bp + 3][bc] = bv.w;
        __syncthreads();
        #pragma unroll
        for (int kk = 0; kk < 16; ++kk) {
            float4 a4 = *(const float4*)&As[kk][tm];
            float4 b4 = *(const float4*)&Bs[kk][tn];
            float aa[4] = {a4.x, a4.y, a4.z, a4.w};
            float bb[4] = {b4.x, b4.y, b4.z, b4.w};
            #pragma unroll
            for (int i = 0; i < 4; ++i)
                #pragma unroll
                for (int j = 0; j < 4; ++j)
                    acc[i][j] = fmaf(aa[i], bb[j], acc[i][j]);
        }
        __syncthreads();
    }
}

// clsWf split-K partials: grid (3, 8, 4)
__global__ __launch_bounds__(256) void k_clsWf(
    const float* __restrict__ cls, const float* __restrict__ W, float* __restrict__ outp)
{
    __shared__ float As[16][64], Bs[16][64];
    const int t = threadIdx.x, k0 = blockIdx.x * 64, c0 = blockIdx.y * 64;
    const int z = blockIdx.z;
    float acc[4][4] = {};
    int av = KCLS - k0; av = av > 64 ? 64 : (av > 0 ? av : 0);
    sg_body(cls + (long)k0 * C, av, W + (long)c0 * C, 64, acc, t, As, Bs,
            z * 128, z * 128 + 128);
    const int tm = (t >> 4) * 4, tn = (t & 15) * 4;
    #pragma unroll
    for (int i = 0; i < 4; ++i) {
        int k = k0 + tm + i;
        if (k < KCLS)
            *(float4*)&outp[(long)z * KCLS * C + (long)k * C + c0 + tn] =
                make_float4(acc[i][0], acc[i][1], acc[i][2], acc[i][3]);
    }
}

__global__ void k_red4(const float* __restrict__ p, float* __restrict__ o)
{
    int i = blockIdx.x * 256 + threadIdx.x;
    if (i < KCLS * C)
        o[i] = p[i] + p[KCLS * C + i] + p[2 * KCLS * C + i] + p[3 * KCLS * C + i];
}

// acls = cls + pool @ Wcls^T (pool already rinv-scaled); emits fp32 + fp16 padded
__global__ __launch_bounds__(256) void k_acls(
    const float* __restrict__ pool, const float* __restrict__ W,
    const float* __restrict__ cls,
    float* __restrict__ outf, u16* __restrict__ outh)
{
    __shared__ float As[16][64], Bs[16][64];
    const int t = threadIdx.x;
    const int k0 = blockIdx.x * 64, c0 = blockIdx.y * 64, b = blockIdx.z;
    float acc[4][4] = {};
    int av = KCLS - k0; av = av > 64 ? 64 : (av > 0 ? av : 0);
    sg_body(pool + ((long)b * KCLS + k0) * C, av, W + (long)c0 * C, 64,
            acc, t, As, Bs, 0, C);
    const int tm = (t >> 4) * 4, tn = (t & 15) * 4;
    #pragma unroll
    for (int i = 0; i < 4; ++i) {
        int k = k0 + tm + i;
        if (k < KCLS) {
            #pragma unroll
            for (int j = 0; j < 4; ++j) {
                float v = acc[i][j] + cls[(long)k * C + c0 + tn + j];
                outf[((long)b * KCLS + k) * C + c0 + tn + j] = v;
                outh[((long)b * KPAD + k) * C + c0 + tn + j] =
                    __half_as_ushort(__float2half_rn(v));
            }
        } else if (k < KPAD) {
            #pragma unroll
            for (int j = 0; j < 4; ++j)
                outh[((long)b * KPAD + k) * C + c0 + tn + j] = 0;
        }
    }
}

__global__ __launch_bounds__(256) void k_G(
    const float* __restrict__ acls, const float* __restrict__ clsWf,
    u16* __restrict__ Gh)
{
    __shared__ float As[16][64], Bs[16][64];
    const int t = threadIdx.x;
    const int k0 = blockIdx.x * 64, k20 = blockIdx.y * 64, b = blockIdx.z;
    float acc[4][4] = {};
    int av = KCLS - k0; av = av > 64 ? 64 : (av > 0 ? av : 0);
    int bv = KCLS - k20; bv = bv > 64 ? 64 : (bv > 0 ? bv : 0);
    sg_body(acls + ((long)b * KCLS + k0) * C, av, clsWf + (long)k20 * C, bv,
            acc, t, As, Bs, 0, C);
    const int tm = (t >> 4) * 4, tn = (t & 15) * 4;
    #pragma unroll
    for (int i = 0; i < 4; ++i) {
        int k = k0 + tm + i;
        if (k < KPAD) {
            #pragma unroll
            for (int j = 0; j < 4; ++j)
                Gh[((long)b * KPAD + k) * KP2 + k20 + tn + j] =
                    __half_as_ushort(__float2half_rn(acc[i][j]));
        }
    }
}

// ===========================================================================
extern "C" void kernel_launch(void* const* d_in, const int* in_sizes, int n_in,
                              void* d_out, int out_size)
{
    const float* x     = (const float*)d_in[0];
    const float* cls   = (const float*)d_in[1];
    const float* Wcls  = (const float*)d_in[2];
    const float* Wfeat = (const float*)d_in[3];
    const float* gamma = (const float*)d_in[4];
    const float* beta  = (const float*)d_in[5];
    float* out = (float*)d_out;

    u16 *clsh, *aclsh, *Gh, *Eh, *xh;
    float *colinv, *rowpart, *rinv, *poolpart, *pool, *acls, *clsWfp, *clsWf;
    cudaGetSymbolAddress((void**)&clsh,  g_clsh);
    cudaGetSymbolAddress((void**)&Eh,    g_Eh);
    cudaGetSymbolAddress((void**)&xh,    g_xh);
    cudaGetSymbolAddress((void**)&colinv, g_colinv);
    cudaGetSymbolAddress((void**)&rowpart, g_rowpart);
    cudaGetSymbolAddress((void**)&rinv,  g_rinv);
    cudaGetSymbolAddress((void**)&poolpart, g_poolpart);
    cudaGetSymbolAddress((void**)&pool,  g_pool);
    cudaGetSymbolAddress((void**)&acls,  g_acls);
    cudaGetSymbolAddress((void**)&aclsh, g_aclsh);
    cudaGetSymbolAddress((void**)&clsWfp, g_clsWfp);
    cudaGetSymbolAddress((void**)&clsWf, g_clsWf);
    cudaGetSymbolAddress((void**)&Gh,    g_Gh);

    cudaFuncSetAttribute(k_gemm1_mma, cudaFuncAttributeMaxDynamicSharedMemorySize, SMEM_N);
    cudaFuncSetAttribute(k_pool_mma,  cudaFuncAttributeMaxDynamicSharedMemorySize, SMEM_N);
    cudaFuncSetAttribute(k_masks_mma, cudaFuncAttributeMaxDynamicSharedMemorySize, SMEM_T);

    k_prep<<<(KPAD * C + 255) / 256, 256>>>(cls, clsh);
    k_gemm1_mma<<<dim3(HW / 128, BATCH), 256, SMEM_N>>>(
        x, clsh, Eh, xh, colinv, rowpart);
    k_rowred<<<(BATCH * KPAD + 255) / 256, 256>>>(rowpart, rinv);
    k_pool_mma<<<dim3(C / 128, NSPLIT, BATCH), 256, SMEM_N>>>(xh, Eh, poolpart);
    k_clsWf<<<dim3(3, C / 64, 4), 256>>>(cls, Wfeat, clsWfp);
    k_red4<<<(KCLS * C + 255) / 256, 256>>>(clsWfp, clsWf);
    k_poolred<<<(int)(((long)BATCH * KCLS * C + 255) / 256), 256>>>(poolpart, rinv, pool);
    k_acls<<<dim3(3, C / 64, BATCH), 256>>>(pool, Wcls, cls, acls, aclsh);
    k_G<<<dim3(3, 3, BATCH), 256>>>(acls, clsWf, Gh);
    k_masks_mma<<<dim3(HW / 128, BATCH), 256, SMEM_T>>>(
        xh, aclsh, Gh, Eh, colinv, gamma, beta, out);
}